// round 1
// baseline (speedup 1.0000x reference)
#include <cuda_runtime.h>
#include <cstdint>
#include <cstddef>

#define N_LOCS 81
#define BATCH  2048
#define EMB    256
#define ELEMS  (BATCH * N_LOCS * EMB)   // 42,467,328

// ---------------- scratch (static device globals; no allocs) ----------------
__device__ float  g_bufA[ELEMS];
__device__ float  g_bufB[ELEMS];
__device__ float  g_bufC[ELEMS];
__device__ double g_sum[N_LOCS];     // zero-initialized at module load
__device__ double g_sumsq[N_LOCS];   // stats kernel re-zeroes after use
__device__ float  g_scale[N_LOCS];
__device__ float  g_shift[N_LOCS];

// ---------------- stage 1: per-node GEMM  Y[b,n,:] = X[b,n,:] @ W_n ----------
#define BM 128
#define BN 128
#define BKT 16
#define TM 8
#define TN 8

__global__ __launch_bounds__(256, 2)
void gemm_node_kernel(const float* __restrict__ X, const float* __restrict__ W,
                      float* __restrict__ Y, int K)
{
    __shared__ float As[BKT][BM];
    __shared__ float Bs[BKT][BN];

    const int n     = blockIdx.z;
    const int mBase = blockIdx.x * BM;   // over BATCH
    const int nBase = blockIdx.y * BN;   // over EMB
    const int ldx   = N_LOCS * K;

    const float* Xn = X + (size_t)n * K;
    const float* Wn = W + (size_t)n * K * EMB;
    float*       Yn = Y + (size_t)n * EMB;

    const int tid  = threadIdx.x;
    const int tRow = (tid >> 4) * TM;
    const int tCol = (tid & 15) * TN;

    const int ar = tid >> 1;           // 0..127 row of X tile
    const int ak = (tid & 1) * 8;      // 0 or 8  k-offset
    const int bk = tid >> 4;           // 0..15   row of W tile
    const int bc = (tid & 15) * 8;     // col of W tile

    float acc[TM][TN];
#pragma unroll
    for (int i = 0; i < TM; i++)
#pragma unroll
        for (int j = 0; j < TN; j++) acc[i][j] = 0.f;

    const int  ksteps = (K + BKT - 1) / BKT;
    const bool fastK  = (K == EMB);

    for (int ks = 0; ks < ksteps; ks++) {
        const int k0 = ks * BKT;
        // ---- X tile (store transposed) ----
        if (fastK) {
            const float4* src = reinterpret_cast<const float4*>(
                Xn + (size_t)(mBase + ar) * ldx + k0 + ak);
            float4 v0 = src[0];
            float4 v1 = src[1];
            As[ak + 0][ar] = v0.x; As[ak + 1][ar] = v0.y;
            As[ak + 2][ar] = v0.z; As[ak + 3][ar] = v0.w;
            As[ak + 4][ar] = v1.x; As[ak + 5][ar] = v1.y;
            As[ak + 6][ar] = v1.z; As[ak + 7][ar] = v1.w;
        } else {
            const float* src = Xn + (size_t)(mBase + ar) * ldx;
#pragma unroll
            for (int u = 0; u < 8; u++) {
                int kidx = k0 + ak + u;
                As[ak + u][ar] = (kidx < K) ? src[kidx] : 0.f;
            }
        }
        // ---- W tile ----
        {
            int kidx = k0 + bk;
            if (kidx < K) {
                const float4* src = reinterpret_cast<const float4*>(
                    Wn + (size_t)kidx * EMB + nBase + bc);
                *reinterpret_cast<float4*>(&Bs[bk][bc])     = src[0];
                *reinterpret_cast<float4*>(&Bs[bk][bc + 4]) = src[1];
            } else {
                float4 z = make_float4(0.f, 0.f, 0.f, 0.f);
                *reinterpret_cast<float4*>(&Bs[bk][bc])     = z;
                *reinterpret_cast<float4*>(&Bs[bk][bc + 4]) = z;
            }
        }
        __syncthreads();
#pragma unroll
        for (int kk = 0; kk < BKT; kk++) {
            float a[TM], b[TN];
#pragma unroll
            for (int i = 0; i < TM; i += 4)
                *reinterpret_cast<float4*>(&a[i]) =
                    *reinterpret_cast<const float4*>(&As[kk][tRow + i]);
#pragma unroll
            for (int j = 0; j < TN; j += 4)
                *reinterpret_cast<float4*>(&b[j]) =
                    *reinterpret_cast<const float4*>(&Bs[kk][tCol + j]);
#pragma unroll
            for (int i = 0; i < TM; i++)
#pragma unroll
                for (int j = 0; j < TN; j++)
                    acc[i][j] = fmaf(a[i], b[j], acc[i][j]);
        }
        __syncthreads();
    }

    const size_t ldy = (size_t)N_LOCS * EMB;
#pragma unroll
    for (int i = 0; i < TM; i++) {
        float* dst = Yn + (size_t)(mBase + tRow + i) * ldy + nBase + tCol;
        *reinterpret_cast<float4*>(dst)     = *reinterpret_cast<float4*>(&acc[i][0]);
        *reinterpret_cast<float4*>(dst + 4) = *reinterpret_cast<float4*>(&acc[i][4]);
    }
}

// ---------------- stage 2: Z[b,m,:] = sum_n A[m,n] Y[b,n,:] + bias, + stats --
// grid: (BATCH, EMB/64), block: (16, 16). o-chunk = 64 floats = 16 float4.
__global__ __launch_bounds__(256)
void mix_kernel(const float* __restrict__ Y, const float* __restrict__ bias,
                float* __restrict__ Z, const float* __restrict__ A)
{
    __shared__ float4 Ys[N_LOCS * 16];
    __shared__ float  sA[N_LOCS * N_LOCS];

    const int b      = blockIdx.x;
    const int oBase4 = blockIdx.y * 16;   // in float4 units
    const int tx  = threadIdx.x;          // 0..15 : o lane (float4)
    const int ty  = threadIdx.y;          // 0..15 : m group
    const int tid = ty * 16 + tx;

    const float4* Yv = reinterpret_cast<const float4*>(Y)
                       + (size_t)b * (N_LOCS * 64) + oBase4;
    for (int idx = tid; idx < N_LOCS * 16; idx += 256) {
        int n = idx >> 4, c = idx & 15;
        Ys[idx] = Yv[(size_t)n * 64 + c];
    }
    for (int idx = tid; idx < N_LOCS * N_LOCS; idx += 256) sA[idx] = A[idx];
    __syncthreads();

    float4 acc[6];
#pragma unroll
    for (int j = 0; j < 6; j++) acc[j] = make_float4(0.f, 0.f, 0.f, 0.f);

    for (int n = 0; n < N_LOCS; n++) {
        float4 y4 = Ys[n * 16 + tx];
#pragma unroll
        for (int j = 0; j < 6; j++) {
            int m = ty + 16 * j;
            if (m < N_LOCS) {
                float a = sA[m * N_LOCS + n];
                acc[j].x = fmaf(a, y4.x, acc[j].x);
                acc[j].y = fmaf(a, y4.y, acc[j].y);
                acc[j].z = fmaf(a, y4.z, acc[j].z);
                acc[j].w = fmaf(a, y4.w, acc[j].w);
            }
        }
    }

    float4 bias4 = reinterpret_cast<const float4*>(bias)[oBase4 + tx];
    float4* Zv = reinterpret_cast<float4*>(Z)
                 + (size_t)b * (N_LOCS * 64) + oBase4 + tx;

#pragma unroll
    for (int j = 0; j < 6; j++) {
        int m = ty + 16 * j;
        if (m >= N_LOCS) break;
        float4 z = acc[j];
        z.x += bias4.x; z.y += bias4.y; z.z += bias4.z; z.w += bias4.w;
        Zv[(size_t)m * 64] = z;

        float s  = z.x + z.y + z.z + z.w;
        float ss = z.x * z.x + z.y * z.y + z.z * z.z + z.w * z.w;
#pragma unroll
        for (int off = 8; off > 0; off >>= 1) {
            s  += __shfl_down_sync(0xffffffffu, s,  off, 16);
            ss += __shfl_down_sync(0xffffffffu, ss, off, 16);
        }
        if (tx == 0) {
            atomicAdd(&g_sum[m],   (double)s);
            atomicAdd(&g_sumsq[m], (double)ss);
        }
    }
}

// ---------------- stats: fold BN into per-node scale/shift; self-zero -------
__global__ void stats_kernel(const float* __restrict__ g, const float* __restrict__ be)
{
    int m = threadIdx.x;
    if (m < N_LOCS) {
        const double cnt  = (double)BATCH * (double)EMB;
        double mean = g_sum[m] / cnt;
        double var  = g_sumsq[m] / cnt - mean * mean;
        if (var < 0.0) var = 0.0;
        double inv = 1.0 / sqrt(var + 1e-5);
        float  sc  = g[m] * (float)inv;
        g_scale[m] = sc;
        g_shift[m] = be[m] - (float)mean * sc;
        g_sum[m]   = 0.0;   // reset for next block / next replay
        g_sumsq[m] = 0.0;
    }
}

// ---------------- stage 3: normalize + relu (+ residual), strided write -----
__global__ __launch_bounds__(256)
void bn_relu_kernel(const float4* __restrict__ Z, const float4* __restrict__ R,
                    float4* __restrict__ Out, int outStrideB4, int outStrideM4)
{
    int i  = blockIdx.x * 256 + threadIdx.x;     // < ELEMS/4 exactly
    int o4 = i & 63;
    int t  = i >> 6;
    int bb = t / N_LOCS;
    int m  = t - bb * N_LOCS;

    float sc = g_scale[m], sh = g_shift[m];
    float4 z = Z[i];
    float4 o;
    o.x = fmaxf(fmaf(z.x, sc, sh), 0.f);
    o.y = fmaxf(fmaf(z.y, sc, sh), 0.f);
    o.z = fmaxf(fmaf(z.z, sc, sh), 0.f);
    o.w = fmaxf(fmaf(z.w, sc, sh), 0.f);
    if (R != nullptr) {
        float4 r = R[i];
        o.x += r.x; o.y += r.y; o.z += r.z; o.w += r.w;
    }
    Out[(size_t)bb * outStrideB4 + (size_t)m * outStrideM4 + o4] = o;
}

// ---------------- host orchestration ----------------------------------------
static void run_stack(const float* x, int K0, const float* A,
                      const float* W0, const float* b0,
                      const float* g0, const float* be0,
                      const float* Ws, const float* bs,
                      const float* gs, const float* bes,
                      float* bufA, float* bufB, float* bufC,
                      float* out /* d_out base + half offset (float) */)
{
    const dim3 gGemm(BATCH / BM, EMB / BN, N_LOCS);
    const dim3 bGemm(256);
    const dim3 gMix(BATCH, EMB / 64);
    const dim3 bMix(16, 16);
    const int  gNorm = ELEMS / 4 / 256;   // 41472

    // block 0 (no residual): x -> bufA -> bufB (in-place normalize)
    gemm_node_kernel<<<gGemm, bGemm>>>(x, W0, bufA, K0);
    mix_kernel<<<gMix, bMix>>>(bufA, b0, bufB, A);
    stats_kernel<<<1, N_LOCS>>>(g0, be0);
    bn_relu_kernel<<<gNorm, 256>>>((const float4*)bufB, nullptr,
                                   (float4*)bufB, N_LOCS * 64, 64);

    const float* cur = bufB;
    float* f0 = bufA;   // y buffer (stable)
    float* f1 = bufC;   // z buffer (rotates with cur)

    for (int i = 0; i < 7; i++) {
        float* y = f0;
        float* z = f1;
        gemm_node_kernel<<<gGemm, bGemm>>>(cur, Ws + (size_t)i * N_LOCS * EMB * EMB,
                                           y, EMB);
        mix_kernel<<<gMix, bMix>>>(y, bs + (size_t)i * EMB, z, A);
        stats_kernel<<<1, N_LOCS>>>(gs + (size_t)i * N_LOCS,
                                    bes + (size_t)i * N_LOCS);
        if (i == 6) {
            // final: write to d_out, node stride 512 floats (=128 float4)
            bn_relu_kernel<<<gNorm, 256>>>((const float4*)z, (const float4*)cur,
                                           (float4*)out, N_LOCS * 128, 128);
        } else {
            bn_relu_kernel<<<gNorm, 256>>>((const float4*)z, (const float4*)cur,
                                           (float4*)z, N_LOCS * 64, 64);
            float* oldcur = const_cast<float*>(cur);
            cur = z;
            f1  = oldcur;
        }
    }
}

extern "C" void kernel_launch(void* const* d_in, const int* in_sizes, int n_in,
                              void* d_out, int out_size)
{
    (void)in_sizes; (void)n_in; (void)out_size;

    const float* x_bo   = (const float*)d_in[0];
    const float* x_po   = (const float*)d_in[1];
    const float* A      = (const float*)d_in[2];
    const float* W0_bo  = (const float*)d_in[3];
    const float* b0_bo  = (const float*)d_in[4];
    const float* g0_bo  = (const float*)d_in[5];
    const float* be0_bo = (const float*)d_in[6];
    const float* W_bo   = (const float*)d_in[7];
    const float* b_bo   = (const float*)d_in[8];
    const float* g_bo   = (const float*)d_in[9];
    const float* be_bo  = (const float*)d_in[10];
    const float* W0_po  = (const float*)d_in[11];
    const float* b0_po  = (const float*)d_in[12];
    const float* g0_po  = (const float*)d_in[13];
    const float* be0_po = (const float*)d_in[14];
    const float* W_po   = (const float*)d_in[15];
    const float* b_po   = (const float*)d_in[16];
    const float* g_po   = (const float*)d_in[17];
    const float* be_po  = (const float*)d_in[18];

    float* out = (float*)d_out;

    float *bufA, *bufB, *bufC;
    cudaGetSymbolAddress((void**)&bufA, g_bufA);
    cudaGetSymbolAddress((void**)&bufB, g_bufB);
    cudaGetSymbolAddress((void**)&bufC, g_bufC);

    // board-state stack -> out[..., 0:256]
    run_stack(x_bo, 35, A, W0_bo, b0_bo, g0_bo, be0_bo,
              W_bo, b_bo, g_bo, be_bo, bufA, bufB, bufC, out);
    // prev-orders stack -> out[..., 256:512]
    run_stack(x_po, 40, A, W0_po, b0_po, g0_po, be0_po,
              W_po, b_po, g_po, be_po, bufA, bufB, bufC, out + EMB);
}

// round 2
// speedup vs baseline: 1.0004x; 1.0004x over previous
#include <cuda_runtime.h>
#include <cstdint>
#include <cstddef>

#define N_LOCS 81
#define BATCH  2048
#define EMB    256
#define ELEMS  (BATCH * N_LOCS * EMB)   // 42,467,328

// ---------------- scratch (static device globals; no allocs) ----------------
__device__ float  g_bufA[ELEMS];
__device__ float  g_bufB[ELEMS];
__device__ float  g_bufC[ELEMS];
__device__ double g_sum[N_LOCS];     // zero-initialized at module load
__device__ double g_sumsq[N_LOCS];   // stats kernel re-zeroes after use
__device__ float  g_scale[N_LOCS];
__device__ float  g_shift[N_LOCS];

// ---------------- stage 1: per-node GEMM  Y[b,n,:] = X[b,n,:] @ W_n ----------
#define BM 128
#define BN 128
#define BKT 16
#define TM 8
#define TN 8

__global__ __launch_bounds__(256, 2)
void gemm_node_kernel(const float* __restrict__ X, const float* __restrict__ W,
                      float* __restrict__ Y, int K)
{
    __shared__ float As[BKT][BM];
    __shared__ float Bs[BKT][BN];

    const int n     = blockIdx.z;
    const int mBase = blockIdx.x * BM;   // over BATCH
    const int nBase = blockIdx.y * BN;   // over EMB
    const int ldx   = N_LOCS * K;

    const float* Xn = X + (size_t)n * K;
    const float* Wn = W + (size_t)n * K * EMB;
    float*       Yn = Y + (size_t)n * EMB;

    const int tid  = threadIdx.x;
    const int tRow = (tid >> 4) * TM;
    const int tCol = (tid & 15) * TN;

    const int ar = tid >> 1;           // 0..127 row of X tile
    const int ak = (tid & 1) * 8;      // 0 or 8  k-offset
    const int bk = tid >> 4;           // 0..15   row of W tile
    const int bc = (tid & 15) * 8;     // col of W tile

    float acc[TM][TN];
#pragma unroll
    for (int i = 0; i < TM; i++)
#pragma unroll
        for (int j = 0; j < TN; j++) acc[i][j] = 0.f;

    const int  ksteps = (K + BKT - 1) / BKT;
    const bool fastK  = (K == EMB);

    for (int ks = 0; ks < ksteps; ks++) {
        const int k0 = ks * BKT;
        // ---- X tile (store transposed) ----
        if (fastK) {
            const float4* src = reinterpret_cast<const float4*>(
                Xn + (size_t)(mBase + ar) * ldx + k0 + ak);
            float4 v0 = src[0];
            float4 v1 = src[1];
            As[ak + 0][ar] = v0.x; As[ak + 1][ar] = v0.y;
            As[ak + 2][ar] = v0.z; As[ak + 3][ar] = v0.w;
            As[ak + 4][ar] = v1.x; As[ak + 5][ar] = v1.y;
            As[ak + 6][ar] = v1.z; As[ak + 7][ar] = v1.w;
        } else {
            const float* src = Xn + (size_t)(mBase + ar) * ldx;
#pragma unroll
            for (int u = 0; u < 8; u++) {
                int kidx = k0 + ak + u;
                As[ak + u][ar] = (kidx < K) ? src[kidx] : 0.f;
            }
        }
        // ---- W tile ----
        {
            int kidx = k0 + bk;
            if (kidx < K) {
                const float4* src = reinterpret_cast<const float4*>(
                    Wn + (size_t)kidx * EMB + nBase + bc);
                *reinterpret_cast<float4*>(&Bs[bk][bc])     = src[0];
                *reinterpret_cast<float4*>(&Bs[bk][bc + 4]) = src[1];
            } else {
                float4 z = make_float4(0.f, 0.f, 0.f, 0.f);
                *reinterpret_cast<float4*>(&Bs[bk][bc])     = z;
                *reinterpret_cast<float4*>(&Bs[bk][bc + 4]) = z;
            }
        }
        __syncthreads();
#pragma unroll
        for (int kk = 0; kk < BKT; kk++) {
            float a[TM], b[TN];
#pragma unroll
            for (int i = 0; i < TM; i += 4)
                *reinterpret_cast<float4*>(&a[i]) =
                    *reinterpret_cast<const float4*>(&As[kk][tRow + i]);
#pragma unroll
            for (int j = 0; j < TN; j += 4)
                *reinterpret_cast<float4*>(&b[j]) =
                    *reinterpret_cast<const float4*>(&Bs[kk][tCol + j]);
#pragma unroll
            for (int i = 0; i < TM; i++)
#pragma unroll
                for (int j = 0; j < TN; j++)
                    acc[i][j] = fmaf(a[i], b[j], acc[i][j]);
        }
        __syncthreads();
    }

    const size_t ldy = (size_t)N_LOCS * EMB;
#pragma unroll
    for (int i = 0; i < TM; i++) {
        float* dst = Yn + (size_t)(mBase + tRow + i) * ldy + nBase + tCol;
        *reinterpret_cast<float4*>(dst)     = *reinterpret_cast<float4*>(&acc[i][0]);
        *reinterpret_cast<float4*>(dst + 4) = *reinterpret_cast<float4*>(&acc[i][4]);
    }
}

// ---------------- stage 2: Z[b,m,:] = sum_n A[m,n] Y[b,n,:] + bias, + stats --
// grid: (BATCH, EMB/64), block: (16, 16). o-chunk = 64 floats = 16 float4.
__global__ __launch_bounds__(256)
void mix_kernel(const float* __restrict__ Y, const float* __restrict__ bias,
                float* __restrict__ Z, const float* __restrict__ A)
{
    __shared__ float4 Ys[N_LOCS * 16];
    __shared__ float  sA[N_LOCS * N_LOCS];

    const int b      = blockIdx.x;
    const int oBase4 = blockIdx.y * 16;   // in float4 units
    const int tx  = threadIdx.x;          // 0..15 : o lane (float4)
    const int ty  = threadIdx.y;          // 0..15 : m group
    const int tid = ty * 16 + tx;

    const float4* Yv = reinterpret_cast<const float4*>(Y)
                       + (size_t)b * (N_LOCS * 64) + oBase4;
    for (int idx = tid; idx < N_LOCS * 16; idx += 256) {
        int n = idx >> 4, c = idx & 15;
        Ys[idx] = Yv[(size_t)n * 64 + c];
    }
    for (int idx = tid; idx < N_LOCS * N_LOCS; idx += 256) sA[idx] = A[idx];
    __syncthreads();

    float4 acc[6];
#pragma unroll
    for (int j = 0; j < 6; j++) acc[j] = make_float4(0.f, 0.f, 0.f, 0.f);

    for (int n = 0; n < N_LOCS; n++) {
        float4 y4 = Ys[n * 16 + tx];
#pragma unroll
        for (int j = 0; j < 6; j++) {
            int m = ty + 16 * j;
            if (m < N_LOCS) {
                float a = sA[m * N_LOCS + n];
                acc[j].x = fmaf(a, y4.x, acc[j].x);
                acc[j].y = fmaf(a, y4.y, acc[j].y);
                acc[j].z = fmaf(a, y4.z, acc[j].z);
                acc[j].w = fmaf(a, y4.w, acc[j].w);
            }
        }
    }

    float4 bias4 = reinterpret_cast<const float4*>(bias)[oBase4 + tx];
    float4* Zv = reinterpret_cast<float4*>(Z)
                 + (size_t)b * (N_LOCS * 64) + oBase4 + tx;

#pragma unroll
    for (int j = 0; j < 6; j++) {
        int m = ty + 16 * j;
        if (m >= N_LOCS) break;
        float4 z = acc[j];
        z.x += bias4.x; z.y += bias4.y; z.z += bias4.z; z.w += bias4.w;
        Zv[(size_t)m * 64] = z;

        float s  = z.x + z.y + z.z + z.w;
        float ss = z.x * z.x + z.y * z.y + z.z * z.z + z.w * z.w;
#pragma unroll
        for (int off = 8; off > 0; off >>= 1) {
            s  += __shfl_down_sync(0xffffffffu, s,  off, 16);
            ss += __shfl_down_sync(0xffffffffu, ss, off, 16);
        }
        if (tx == 0) {
            atomicAdd(&g_sum[m],   (double)s);
            atomicAdd(&g_sumsq[m], (double)ss);
        }
    }
}

// ---------------- stats: fold BN into per-node scale/shift; self-zero -------
__global__ void stats_kernel(const float* __restrict__ g, const float* __restrict__ be)
{
    int m = threadIdx.x;
    if (m < N_LOCS) {
        const double cnt  = (double)BATCH * (double)EMB;
        double mean = g_sum[m] / cnt;
        double var  = g_sumsq[m] / cnt - mean * mean;
        if (var < 0.0) var = 0.0;
        double inv = 1.0 / sqrt(var + 1e-5);
        float  sc  = g[m] * (float)inv;
        g_scale[m] = sc;
        g_shift[m] = be[m] - (float)mean * sc;
        g_sum[m]   = 0.0;   // reset for next block / next replay
        g_sumsq[m] = 0.0;
    }
}

// ---------------- stage 3: normalize + relu (+ residual), strided write -----
__global__ __launch_bounds__(256)
void bn_relu_kernel(const float4* __restrict__ Z, const float4* __restrict__ R,
                    float4* __restrict__ Out, int outStrideB4, int outStrideM4)
{
    int i  = blockIdx.x * 256 + threadIdx.x;     // < ELEMS/4 exactly
    int o4 = i & 63;
    int t  = i >> 6;
    int bb = t / N_LOCS;
    int m  = t - bb * N_LOCS;

    float sc = g_scale[m], sh = g_shift[m];
    float4 z = Z[i];
    float4 o;
    o.x = fmaxf(fmaf(z.x, sc, sh), 0.f);
    o.y = fmaxf(fmaf(z.y, sc, sh), 0.f);
    o.z = fmaxf(fmaf(z.z, sc, sh), 0.f);
    o.w = fmaxf(fmaf(z.w, sc, sh), 0.f);
    if (R != nullptr) {
        float4 r = R[i];
        o.x += r.x; o.y += r.y; o.z += r.z; o.w += r.w;
    }
    Out[(size_t)bb * outStrideB4 + (size_t)m * outStrideM4 + o4] = o;
}

// ---------------- host orchestration ----------------------------------------
static void run_stack(const float* x, int K0, const float* A,
                      const float* W0, const float* b0,
                      const float* g0, const float* be0,
                      const float* Ws, const float* bs,
                      const float* gs, const float* bes,
                      float* bufA, float* bufB, float* bufC,
                      float* out /* d_out base + half offset (float) */)
{
    const dim3 gGemm(BATCH / BM, EMB / BN, N_LOCS);
    const dim3 bGemm(256);
    const dim3 gMix(BATCH, EMB / 64);
    const dim3 bMix(16, 16);
    const int  gNorm = ELEMS / 4 / 256;   // 41472

    // block 0 (no residual): x -> bufA -> bufB (in-place normalize)
    gemm_node_kernel<<<gGemm, bGemm>>>(x, W0, bufA, K0);
    mix_kernel<<<gMix, bMix>>>(bufA, b0, bufB, A);
    stats_kernel<<<1, N_LOCS>>>(g0, be0);
    bn_relu_kernel<<<gNorm, 256>>>((const float4*)bufB, nullptr,
                                   (float4*)bufB, N_LOCS * 64, 64);

    const float* cur = bufB;
    float* f0 = bufA;   // y buffer (stable)
    float* f1 = bufC;   // z buffer (rotates with cur)

    for (int i = 0; i < 7; i++) {
        float* y = f0;
        float* z = f1;
        gemm_node_kernel<<<gGemm, bGemm>>>(cur, Ws + (size_t)i * N_LOCS * EMB * EMB,
                                           y, EMB);
        mix_kernel<<<gMix, bMix>>>(y, bs + (size_t)i * EMB, z, A);
        stats_kernel<<<1, N_LOCS>>>(gs + (size_t)i * N_LOCS,
                                    bes + (size_t)i * N_LOCS);
        if (i == 6) {
            // final: write to d_out, node stride 512 floats (=128 float4)
            bn_relu_kernel<<<gNorm, 256>>>((const float4*)z, (const float4*)cur,
                                           (float4*)out, N_LOCS * 128, 128);
        } else {
            bn_relu_kernel<<<gNorm, 256>>>((const float4*)z, (const float4*)cur,
                                           (float4*)z, N_LOCS * 64, 64);
            float* oldcur = const_cast<float*>(cur);
            cur = z;
            f1  = oldcur;
        }
    }
}

extern "C" void kernel_launch(void* const* d_in, const int* in_sizes, int n_in,
                              void* d_out, int out_size)
{
    (void)in_sizes; (void)n_in; (void)out_size;

    const float* x_bo   = (const float*)d_in[0];
    const float* x_po   = (const float*)d_in[1];
    const float* A      = (const float*)d_in[2];
    const float* W0_bo  = (const float*)d_in[3];
    const float* b0_bo  = (const float*)d_in[4];
    const float* g0_bo  = (const float*)d_in[5];
    const float* be0_bo = (const float*)d_in[6];
    const float* W_bo   = (const float*)d_in[7];
    const float* b_bo   = (const float*)d_in[8];
    const float* g_bo   = (const float*)d_in[9];
    const float* be_bo  = (const float*)d_in[10];
    const float* W0_po  = (const float*)d_in[11];
    const float* b0_po  = (const float*)d_in[12];
    const float* g0_po  = (const float*)d_in[13];
    const float* be0_po = (const float*)d_in[14];
    const float* W_po   = (const float*)d_in[15];
    const float* b_po   = (const float*)d_in[16];
    const float* g_po   = (const float*)d_in[17];
    const float* be_po  = (const float*)d_in[18];

    float* out = (float*)d_out;

    float *bufA, *bufB, *bufC;
    cudaGetSymbolAddress((void**)&bufA, g_bufA);
    cudaGetSymbolAddress((void**)&bufB, g_bufB);
    cudaGetSymbolAddress((void**)&bufC, g_bufC);

    // board-state stack -> out[..., 0:256]
    run_stack(x_bo, 35, A, W0_bo, b0_bo, g0_bo, be0_bo,
              W_bo, b_bo, g_bo, be_bo, bufA, bufB, bufC, out);
    // prev-orders stack -> out[..., 256:512]
    run_stack(x_po, 40, A, W0_po, b0_po, g0_po, be0_po,
              W_po, b_po, g_po, be_po, bufA, bufB, bufC, out + EMB);
}

// round 4
// speedup vs baseline: 1.2751x; 1.2745x over previous
#include <cuda_runtime.h>
#include <cuda_bf16.h>
#include <cstdint>
#include <cstddef>

#define N_LOCS 81
#define BATCH  2048
#define EMB    256
#define ELEMS  (BATCH * N_LOCS * EMB)
#define WS_ELEMS (7 * N_LOCS * EMB * EMB)
#define W0_ELEMS (N_LOCS * EMB * 64)

__device__ float  g_bufA[ELEMS];
__device__ float  g_bufB[ELEMS];
__device__ __nv_bfloat16 g_ah0[ELEMS];
__device__ __nv_bfloat16 g_al0[ELEMS];
__device__ __nv_bfloat16 g_ah1[ELEMS];
__device__ __nv_bfloat16 g_al1[ELEMS];
__device__ __nv_bfloat16 g_wth[WS_ELEMS];
__device__ __nv_bfloat16 g_wtl[WS_ELEMS];
__device__ __nv_bfloat16 g_w0h[W0_ELEMS];
__device__ __nv_bfloat16 g_w0l[W0_ELEMS];
__device__ double g_sum[N_LOCS];
__device__ double g_sumsq[N_LOCS];
__device__ float  g_scale[N_LOCS];
__device__ float  g_shift[N_LOCS];

__device__ __forceinline__ uint32_t s2u(const void* p) {
    uint32_t a;
    asm("{ .reg .u64 t; cvta.to.shared.u64 t, %1; cvt.u32.u64 %0, t; }" : "=r"(a) : "l"(p));
    return a;
}
__device__ __forceinline__ void cp16(uint32_t s, const void* g) {
    asm volatile("cp.async.cg.shared.global [%0], [%1], 16;" :: "r"(s), "l"(g) : "memory");
}
__device__ __forceinline__ void cp_commit() {
    asm volatile("cp.async.commit_group;" ::: "memory");
}
template <int N>
__device__ __forceinline__ void cp_wait() {
    asm volatile("cp.async.wait_group %0;" :: "n"(N) : "memory");
}
#define LDSM_X4(r0, r1, r2, r3, addr) \
    asm volatile("ldmatrix.sync.aligned.m8n8.x4.shared.b16 {%0,%1,%2,%3}, [%4];" \
                 : "=r"(r0), "=r"(r1), "=r"(r2), "=r"(r3) : "r"(addr))
#define LDSM_X2(r0, r1, addr) \
    asm volatile("ldmatrix.sync.aligned.m8n8.x2.shared.b16 {%0,%1}, [%2];" \
                 : "=r"(r0), "=r"(r1) : "r"(addr))
#define MMA_BF16(d, a, b) \
    asm volatile("mma.sync.aligned.m16n8k16.row.col.f32.bf16.bf16.f32 " \
                 "{%0,%1,%2,%3}, {%4,%5,%6,%7}, {%8,%9}, {%0,%1,%2,%3};" \
                 : "+f"((d)[0]), "+f"((d)[1]), "+f"((d)[2]), "+f"((d)[3]) \
                 : "r"((a)[0]), "r"((a)[1]), "r"((a)[2]), "r"((a)[3]), \
                   "r"((b)[0]), "r"((b)[1]))

// smem: per-stage 40960 B: Ah(128x80) Al Bh Bl; two stages = 81920 B
#define ROWB   80
#define TILE_B 10240
#define STAGE_B 40960
#define GEMM_SMEM (2 * STAGE_B)

// ---------------- stage 1: per-node GEMM via HMMA (bf16 2-way split) --------
__global__ __launch_bounds__(256, 2)
void gemm_mma_kernel(const __nv_bfloat16* __restrict__ Xh, const __nv_bfloat16* __restrict__ Xl,
                     const __nv_bfloat16* __restrict__ Wh, const __nv_bfloat16* __restrict__ Wl,
                     float* __restrict__ Y, int K, int Kpad)
{
    extern __shared__ char smem[];
    const uint32_t sb = s2u(smem);
    const int tid  = threadIdx.x;
    const int wid  = tid >> 5;
    const int lane = tid & 31;
    const int wm   = wid >> 2;          // 0..1  (64 rows)
    const int wn   = wid & 3;           // 0..3  (32 cols)
    const int n     = blockIdx.z;
    const int mBase = blockIdx.x * 128;
    const int nBase = blockIdx.y * 128;
    const int ldx   = N_LOCS * K;
    const bool fastK = (K == EMB);

    const __nv_bfloat16* Xhn = Xh + (size_t)n * K;
    const __nv_bfloat16* Xln = Xl + (size_t)n * K;
    const __nv_bfloat16* Whn = Wh + (size_t)n * EMB * Kpad;
    const __nv_bfloat16* Wln = Wl + (size_t)n * EMB * Kpad;

    float acc[4][4][4];
#pragma unroll
    for (int mt = 0; mt < 4; mt++)
#pragma unroll
        for (int nt = 0; nt < 4; nt++)
#pragma unroll
            for (int q = 0; q < 4; q++) acc[mt][nt][q] = 0.f;

    const int nchunk = Kpad >> 5;   // K-chunks of 32

    // ---- loader (chunk c -> stage c&1) ----
    auto load_chunk = [&](int c) {
        const uint32_t st = sb + (c & 1) * STAGE_B;
        const int k0 = c << 5;
        if (fastK) {
#pragma unroll
            for (int it = 0; it < 2; it++) {
                int idx = tid + (it << 8);          // 0..511
                int r = idx >> 2, j = idx & 3;
                size_t go = (size_t)(mBase + r) * ldx + k0 + j * 8;
                uint32_t so = st + r * ROWB + j * 16;
                cp16(so,           Xhn + go);
                cp16(so + TILE_B,  Xln + go);
            }
        } else {
            // small-K: synchronous zero-padded scalar loads (block 0 only)
            for (int it = 0; it < 16; it++) {
                int idx = tid + (it << 8);          // 0..4095
                int r = idx >> 5, kk = idx & 31;
                int k = k0 + kk;
                __nv_bfloat16 vh = __float2bfloat16(0.f), vl = vh;
                if (k < K) {
                    size_t go = (size_t)(mBase + r) * ldx + k;
                    vh = Xhn[go]; vl = Xln[go];
                }
                uint32_t so = st + r * ROWB + kk * 2;
                *reinterpret_cast<__nv_bfloat16*>(smem + (so - sb))          = vh;
                *reinterpret_cast<__nv_bfloat16*>(smem + (so - sb) + TILE_B) = vl;
            }
        }
#pragma unroll
        for (int it = 0; it < 2; it++) {
            int idx = tid + (it << 8);
            int r = idx >> 2, j = idx & 3;
            size_t go = (size_t)(nBase + r) * Kpad + k0 + j * 8;
            uint32_t so = st + 2 * TILE_B + r * ROWB + j * 16;
            cp16(so,          Whn + go);
            cp16(so + TILE_B, Wln + go);
        }
        cp_commit();
    };

    load_chunk(0);

    for (int c = 0; c < nchunk; c++) {
        if (c + 1 < nchunk) { load_chunk(c + 1); cp_wait<1>(); }
        else                { cp_wait<0>(); }
        __syncthreads();

        const uint32_t st  = sb + (c & 1) * STAGE_B;
        const uint32_t sAh = st;
        const uint32_t sAl = st + TILE_B;
        const uint32_t sBh = st + 2 * TILE_B;
        const uint32_t sBl = st + 3 * TILE_B;

#pragma unroll
        for (int ks = 0; ks < 2; ks++) {
            uint32_t bh[4][2], bl[4][2];
            const uint32_t bOff = (wn * 32 + (lane & 7)) * ROWB
                                  + ks * 32 + ((lane >> 3) & 1) * 16;
#pragma unroll
            for (int nt = 0; nt < 4; nt++) {
                LDSM_X2(bh[nt][0], bh[nt][1], sBh + bOff + nt * 8 * ROWB);
                LDSM_X2(bl[nt][0], bl[nt][1], sBl + bOff + nt * 8 * ROWB);
            }
            const uint32_t aOff = (wm * 64 + (lane & 15)) * ROWB
                                  + ks * 32 + (lane >> 4) * 16;
#pragma unroll
            for (int mt = 0; mt < 4; mt++) {
                uint32_t ah[4], al[4];
                LDSM_X4(ah[0], ah[1], ah[2], ah[3], sAh + aOff + mt * 16 * ROWB);
                LDSM_X4(al[0], al[1], al[2], al[3], sAl + aOff + mt * 16 * ROWB);
#pragma unroll
                for (int nt = 0; nt < 4; nt++) {
                    MMA_BF16(acc[mt][nt], ah, bh[nt]);
                    MMA_BF16(acc[mt][nt], ah, bl[nt]);
                    MMA_BF16(acc[mt][nt], al, bh[nt]);
                }
            }
        }
        __syncthreads();
    }

    // ---- epilogue: Y[b][n][o] fp32 ----
#pragma unroll
    for (int mt = 0; mt < 4; mt++) {
        int row0 = mBase + wm * 64 + mt * 16 + (lane >> 2);
#pragma unroll
        for (int nt = 0; nt < 4; nt++) {
            int col = nBase + wn * 32 + nt * 8 + 2 * (lane & 3);
            float* d0 = Y + ((size_t)row0 * N_LOCS + n) * EMB + col;
            float* d1 = Y + ((size_t)(row0 + 8) * N_LOCS + n) * EMB + col;
            *reinterpret_cast<float2*>(d0) = make_float2(acc[mt][nt][0], acc[mt][nt][1]);
            *reinterpret_cast<float2*>(d1) = make_float2(acc[mt][nt][2], acc[mt][nt][3]);
        }
    }
}

// ---------------- stage 2: adjacency mix + BN stats (f32x2) ------------------
__global__ __launch_bounds__(256)
void mix_kernel(const float* __restrict__ Y, const float* __restrict__ bias,
                float* __restrict__ Z, const float* __restrict__ A)
{
    __shared__ float4 Ys[N_LOCS * 16];
    __shared__ float  sA[N_LOCS * N_LOCS];
    const int b = blockIdx.x, oBase4 = blockIdx.y * 16;
    const int tx = threadIdx.x, ty = threadIdx.y, tid = ty * 16 + tx;

    const float4* Yv = reinterpret_cast<const float4*>(Y) + (size_t)b * (N_LOCS * 64) + oBase4;
    for (int idx = tid; idx < N_LOCS * 16; idx += 256)
        Ys[idx] = Yv[(size_t)(idx >> 4) * 64 + (idx & 15)];
    for (int idx = tid; idx < N_LOCS * N_LOCS; idx += 256) sA[idx] = A[idx];
    __syncthreads();

    unsigned long long acc01[6], acc23[6];
#pragma unroll
    for (int j = 0; j < 6; j++) { acc01[j] = 0ull; acc23[j] = 0ull; }
    for (int n = 0; n < N_LOCS; n++) {
        float4 y4 = Ys[n * 16 + tx];
        unsigned long long y01, y23;
        asm("mov.b64 %0, {%1, %2};" : "=l"(y01)
            : "r"(__float_as_uint(y4.x)), "r"(__float_as_uint(y4.y)));
        asm("mov.b64 %0, {%1, %2};" : "=l"(y23)
            : "r"(__float_as_uint(y4.z)), "r"(__float_as_uint(y4.w)));
#pragma unroll
        for (int j = 0; j < 6; j++) {
            int m = ty + 16 * j;
            if (m < N_LOCS) {
                unsigned long long a2;
                asm("mov.b64 %0, {%1, %1};" : "=l"(a2)
                    : "r"(__float_as_uint(sA[m * N_LOCS + n])));
                asm("fma.rn.f32x2 %0, %1, %2, %0;" : "+l"(acc01[j]) : "l"(a2), "l"(y01));
                asm("fma.rn.f32x2 %0, %1, %2, %0;" : "+l"(acc23[j]) : "l"(a2), "l"(y23));
            }
        }
    }
    float4 bias4 = reinterpret_cast<const float4*>(bias)[oBase4 + tx];
    float4* Zv = reinterpret_cast<float4*>(Z) + (size_t)b * (N_LOCS * 64) + oBase4 + tx;
#pragma unroll
    for (int j = 0; j < 6; j++) {
        int m = ty + 16 * j;
        if (m >= N_LOCS) break;
        uint32_t zx, zy, zz, zw;
        asm("mov.b64 {%0, %1}, %2;" : "=r"(zx), "=r"(zy) : "l"(acc01[j]));
        asm("mov.b64 {%0, %1}, %2;" : "=r"(zz), "=r"(zw) : "l"(acc23[j]));
        float4 z;
        z.x = __uint_as_float(zx) + bias4.x;
        z.y = __uint_as_float(zy) + bias4.y;
        z.z = __uint_as_float(zz) + bias4.z;
        z.w = __uint_as_float(zw) + bias4.w;
        Zv[(size_t)m * 64] = z;
        float s  = z.x + z.y + z.z + z.w;
        float ss = z.x * z.x + z.y * z.y + z.z * z.z + z.w * z.w;
#pragma unroll
        for (int off = 8; off > 0; off >>= 1) {
            s  += __shfl_down_sync(0xffffffffu, s,  off, 16);
            ss += __shfl_down_sync(0xffffffffu, ss, off, 16);
        }
        if (tx == 0) {
            atomicAdd(&g_sum[m],   (double)s);
            atomicAdd(&g_sumsq[m], (double)ss);
        }
    }
}

__global__ void stats_kernel(const float* __restrict__ g, const float* __restrict__ be)
{
    int m = threadIdx.x;
    if (m < N_LOCS) {
        const double cnt = (double)BATCH * (double)EMB;
        double mean = g_sum[m] / cnt;
        double var  = g_sumsq[m] / cnt - mean * mean;
        if (var < 0.0) var = 0.0;
        double inv = 1.0 / sqrt(var + 1e-5);
        float sc = g[m] * (float)inv;
        g_scale[m] = sc;
        g_shift[m] = be[m] - (float)mean * sc;
        g_sum[m] = 0.0; g_sumsq[m] = 0.0;
    }
}

// ---------------- stage 3: normalize + relu (+ hi/lo residual) ---------------
__device__ __forceinline__ uint32_t pack2bf(float a, float b) {
    __nv_bfloat162 t;
    t.x = __float2bfloat16(a); t.y = __float2bfloat16(b);
    return *reinterpret_cast<uint32_t*>(&t);
}

__global__ __launch_bounds__(256)
void bn_relu_kernel(const float4* __restrict__ Z,
                    const __nv_bfloat16* __restrict__ Rh, const __nv_bfloat16* __restrict__ Rl,
                    float4* __restrict__ OutF,
                    __nv_bfloat16* __restrict__ Oh, __nv_bfloat16* __restrict__ Ol,
                    int sB4, int sM4)
{
    int i  = blockIdx.x * 256 + threadIdx.x;
    int o4 = i & 63, t = i >> 6;
    int bb = t / N_LOCS, m = t - bb * N_LOCS;
    float sc = g_scale[m], sh = g_shift[m];
    float4 z = Z[i];
    float4 o;
    o.x = fmaxf(fmaf(z.x, sc, sh), 0.f);
    o.y = fmaxf(fmaf(z.y, sc, sh), 0.f);
    o.z = fmaxf(fmaf(z.z, sc, sh), 0.f);
    o.w = fmaxf(fmaf(z.w, sc, sh), 0.f);
    if (Rh != nullptr) {
        uint2 RH = reinterpret_cast<const uint2*>(Rh)[i];
        uint2 RL = reinterpret_cast<const uint2*>(Rl)[i];
        __nv_bfloat162 h0 = *reinterpret_cast<__nv_bfloat162*>(&RH.x);
        __nv_bfloat162 h1 = *reinterpret_cast<__nv_bfloat162*>(&RH.y);
        __nv_bfloat162 l0 = *reinterpret_cast<__nv_bfloat162*>(&RL.x);
        __nv_bfloat162 l1 = *reinterpret_cast<__nv_bfloat162*>(&RL.y);
        o.x += __bfloat162float(h0.x) + __bfloat162float(l0.x);
        o.y += __bfloat162float(h0.y) + __bfloat162float(l0.y);
        o.z += __bfloat162float(h1.x) + __bfloat162float(l1.x);
        o.w += __bfloat162float(h1.y) + __bfloat162float(l1.y);
    }
    if (OutF != nullptr) {
        OutF[(size_t)bb * sB4 + (size_t)m * sM4 + o4] = o;
    } else {
        float hx = __bfloat162float(__float2bfloat16(o.x));
        float hy = __bfloat162float(__float2bfloat16(o.y));
        float hz = __bfloat162float(__float2bfloat16(o.z));
        float hw = __bfloat162float(__float2bfloat16(o.w));
        uint2 H, L;
        H.x = pack2bf(hx, hy); H.y = pack2bf(hz, hw);
        L.x = pack2bf(o.x - hx, o.y - hy); L.y = pack2bf(o.z - hz, o.w - hw);
        reinterpret_cast<uint2*>(Oh)[i] = H;
        reinterpret_cast<uint2*>(Ol)[i] = L;
    }
}

// ---------------- weight transpose+split: [nm,K,256] -> [nm,256,Kpad] --------
__global__ void tconv_kernel(const float* __restrict__ W,
                             __nv_bfloat16* __restrict__ oh, __nv_bfloat16* __restrict__ ol,
                             int K, int Kpad)
{
    __shared__ float t[32][33];
    int nm = blockIdx.x, ob = blockIdx.y * 32, kb = blockIdx.z * 32;
    const float* Wn = W + (size_t)nm * K * EMB;
    for (int r = threadIdx.y; r < 32; r += 8) {
        int k = kb + r;
        t[r][threadIdx.x] = (k < K) ? Wn[(size_t)k * EMB + ob + threadIdx.x] : 0.f;
    }
    __syncthreads();
    size_t obase = (size_t)nm * EMB * Kpad;
    for (int r = threadIdx.y; r < 32; r += 8) {
        float v = t[threadIdx.x][r];
        __nv_bfloat16 h = __float2bfloat16(v);
        size_t d = obase + (size_t)(ob + r) * Kpad + kb + threadIdx.x;
        oh[d] = h;
        ol[d] = __float2bfloat16(v - __bfloat162float(h));
    }
}

__global__ void split_kernel(const float* __restrict__ x,
                             __nv_bfloat16* __restrict__ h, __nv_bfloat16* __restrict__ l, int n)
{
    int i = blockIdx.x * 256 + threadIdx.x;
    if (i < n) {
        float v = x[i];
        __nv_bfloat16 hh = __float2bfloat16(v);
        h[i] = hh;
        l[i] = __float2bfloat16(v - __bfloat162float(hh));
    }
}

// ---------------- host orchestration ----------------------------------------
static void run_stack(const float* x, int K0, const float* A,
                      const float* W0, const float* b0, const float* g0, const float* be0,
                      const float* Ws, const float* bs, const float* gs, const float* bes,
                      float* bufA, float* bufB,
                      __nv_bfloat16* ah0, __nv_bfloat16* al0,
                      __nv_bfloat16* ah1, __nv_bfloat16* al1,
                      __nv_bfloat16* wth, __nv_bfloat16* wtl,
                      __nv_bfloat16* w0h, __nv_bfloat16* w0l, float* outF)
{
    dim3 tcb(32, 8);
    tconv_kernel<<<dim3(N_LOCS, 8, 2), tcb>>>(W0, w0h, w0l, K0, 64);
    tconv_kernel<<<dim3(7 * N_LOCS, 8, 8), tcb>>>(Ws, wth, wtl, EMB, EMB);
    int nx = BATCH * N_LOCS * K0;
    split_kernel<<<(nx + 255) / 256, 256>>>(x, ah0, al0, nx);

    const dim3 gG(BATCH / 128, EMB / 128, N_LOCS);
    const dim3 gMix(BATCH, EMB / 64);
    const dim3 bMix(16, 16);
    const int  gNorm = ELEMS / 4 / 256;
    __nv_bfloat16* AH[2] = { ah0, ah1 };
    __nv_bfloat16* AL[2] = { al0, al1 };

    gemm_mma_kernel<<<gG, 256, GEMM_SMEM>>>(ah0, al0, w0h, w0l, bufA, K0, 64);
    mix_kernel<<<gMix, bMix>>>(bufA, b0, bufB, A);
    stats_kernel<<<1, N_LOCS>>>(g0, be0);
    bn_relu_kernel<<<gNorm, 256>>>((const float4*)bufB, nullptr, nullptr,
                                   nullptr, ah1, al1, 0, 0);
    for (int bi = 1; bi <= 7; bi++) {
        int i = bi - 1, r = bi & 1, w = (bi + 1) & 1;
        gemm_mma_kernel<<<gG, 256, GEMM_SMEM>>>(
            AH[r], AL[r],
            wth + (size_t)i * N_LOCS * EMB * EMB, wtl + (size_t)i * N_LOCS * EMB * EMB,
            bufA, EMB, EMB);
        mix_kernel<<<gMix, bMix>>>(bufA, bs + (size_t)i * EMB, bufB, A);
        stats_kernel<<<1, N_LOCS>>>(gs + (size_t)i * N_LOCS, bes + (size_t)i * N_LOCS);
        if (bi == 7)
            bn_relu_kernel<<<gNorm, 256>>>((const float4*)bufB, AH[r], AL[r],
                                           (float4*)outF, nullptr, nullptr,
                                           N_LOCS * 128, 128);
        else
            bn_relu_kernel<<<gNorm, 256>>>((const float4*)bufB, AH[r], AL[r],
                                           nullptr, AH[w], AL[w], 0, 0);
    }
}

extern "C" void kernel_launch(void* const* d_in, const int* in_sizes, int n_in,
                              void* d_out, int out_size)
{
    (void)in_sizes; (void)n_in; (void)out_size;
    const float* x_bo   = (const float*)d_in[0];
    const float* x_po   = (const float*)d_in[1];
    const float* A      = (const float*)d_in[2];
    const float* W0_bo  = (const float*)d_in[3];
    const float* b0_bo  = (const float*)d_in[4];
    const float* g0_bo  = (const float*)d_in[5];
    const float* be0_bo = (const float*)d_in[6];
    const float* W_bo   = (const float*)d_in[7];
    const float* b_bo   = (const float*)d_in[8];
    const float* g_bo   = (const float*)d_in[9];
    const float* be_bo  = (const float*)d_in[10];
    const float* W0_po  = (const float*)d_in[11];
    const float* b0_po  = (const float*)d_in[12];
    const float* g0_po  = (const float*)d_in[13];
    const float* be0_po = (const float*)d_in[14];
    const float* W_po   = (const float*)d_in[15];
    const float* b_po   = (const float*)d_in[16];
    const float* g_po   = (const float*)d_in[17];
    const float* be_po  = (const float*)d_in[18];
    float* out = (float*)d_out;

    cudaFuncSetAttribute(gemm_mma_kernel,
                         cudaFuncAttributeMaxDynamicSharedMemorySize, GEMM_SMEM);

    float *bufA, *bufB;
    __nv_bfloat16 *ah0, *al0, *ah1, *al1, *wth, *wtl, *w0h, *w0l;
    cudaGetSymbolAddress((void**)&bufA, g_bufA);
    cudaGetSymbolAddress((void**)&bufB, g_bufB);
    cudaGetSymbolAddress((void**)&ah0, g_ah0);
    cudaGetSymbolAddress((void**)&al0, g_al0);
    cudaGetSymbolAddress((void**)&ah1, g_ah1);
    cudaGetSymbolAddress((void**)&al1, g_al1);
    cudaGetSymbolAddress((void**)&wth, g_wth);
    cudaGetSymbolAddress((void**)&wtl, g_wtl);
    cudaGetSymbolAddress((void**)&w0h, g_w0h);
    cudaGetSymbolAddress((void**)&w0l, g_w0l);

    run_stack(x_bo, 35, A, W0_bo, b0_bo, g0_bo, be0_bo, W_bo, b_bo, g_bo, be_bo,
              bufA, bufB, ah0, al0, ah1, al1, wth, wtl, w0h, w0l, out);
    run_stack(x_po, 40, A, W0_po, b0_po, g0_po, be0_po, W_po, b_po, g_po, be_po,
              bufA, bufB, ah0, al0, ah1, al1, wth, wtl, w0h, w0l, out + EMB);
}

// round 5
// speedup vs baseline: 1.8755x; 1.4709x over previous
#include <cuda_runtime.h>
#include <cuda_bf16.h>
#include <cstdint>
#include <cstddef>

#define N_LOCS 81
#define BATCH  2048
#define EMB    256
#define ELEMS  (BATCH * N_LOCS * EMB)
#define WS_ELEMS (7 * N_LOCS * EMB * EMB)
#define W0_ELEMS (N_LOCS * EMB * 64)

__device__ float  g_bufB[ELEMS];                 // Z (mix output, fp32)
__device__ __nv_bfloat16 g_yh[ELEMS];            // Y hi/lo (gemm output)
__device__ __nv_bfloat16 g_yl[ELEMS];
__device__ __nv_bfloat16 g_ah0[ELEMS];
__device__ __nv_bfloat16 g_al0[ELEMS];
__device__ __nv_bfloat16 g_ah1[ELEMS];
__device__ __nv_bfloat16 g_al1[ELEMS];
__device__ __nv_bfloat16 g_wth[WS_ELEMS];
__device__ __nv_bfloat16 g_wtl[WS_ELEMS];
__device__ __nv_bfloat16 g_w0h[W0_ELEMS];
__device__ __nv_bfloat16 g_w0l[W0_ELEMS];
__device__ __nv_bfloat16 g_Ah96[96 * 96];        // padded split adjacency
__device__ __nv_bfloat16 g_Al96[96 * 96];
__device__ double g_sum[N_LOCS];
__device__ double g_sumsq[N_LOCS];
__device__ float  g_scale[N_LOCS];
__device__ float  g_shift[N_LOCS];

__device__ __forceinline__ uint32_t s2u(const void* p) {
    uint32_t a;
    asm("{ .reg .u64 t; cvta.to.shared.u64 t, %1; cvt.u32.u64 %0, t; }" : "=r"(a) : "l"(p));
    return a;
}
__device__ __forceinline__ void cp16(uint32_t s, const void* g) {
    asm volatile("cp.async.cg.shared.global [%0], [%1], 16;" :: "r"(s), "l"(g) : "memory");
}
__device__ __forceinline__ void cp_commit() {
    asm volatile("cp.async.commit_group;" ::: "memory");
}
template <int N>
__device__ __forceinline__ void cp_wait() {
    asm volatile("cp.async.wait_group %0;" :: "n"(N) : "memory");
}
#define LDSM_X4(r0, r1, r2, r3, addr) \
    asm volatile("ldmatrix.sync.aligned.m8n8.x4.shared.b16 {%0,%1,%2,%3}, [%4];" \
                 : "=r"(r0), "=r"(r1), "=r"(r2), "=r"(r3) : "r"(addr))
#define LDSM_X2(r0, r1, addr) \
    asm volatile("ldmatrix.sync.aligned.m8n8.x2.shared.b16 {%0,%1}, [%2];" \
                 : "=r"(r0), "=r"(r1) : "r"(addr))
#define LDSM_X2T(r0, r1, addr) \
    asm volatile("ldmatrix.sync.aligned.m8n8.x2.trans.shared.b16 {%0,%1}, [%2];" \
                 : "=r"(r0), "=r"(r1) : "r"(addr))
#define MMA_BF16(d, a, b) \
    asm volatile("mma.sync.aligned.m16n8k16.row.col.f32.bf16.bf16.f32 " \
                 "{%0,%1,%2,%3}, {%4,%5,%6,%7}, {%8,%9}, {%0,%1,%2,%3};" \
                 : "+f"((d)[0]), "+f"((d)[1]), "+f"((d)[2]), "+f"((d)[3]) \
                 : "r"((a)[0]), "r"((a)[1]), "r"((a)[2]), "r"((a)[3]), \
                   "r"((b)[0]), "r"((b)[1]))

__device__ __forceinline__ uint32_t pack2bf(float a, float b) {
    __nv_bfloat162 t;
    t.x = __float2bfloat16(a); t.y = __float2bfloat16(b);
    return *reinterpret_cast<uint32_t*>(&t);
}

// ==================== stage 1: per-node GEMM via HMMA ========================
#define ROWB   80
#define TILE_B 10240
#define STAGE_B 40960
#define GEMM_SMEM (2 * STAGE_B)

__global__ __launch_bounds__(256, 2)
void gemm_mma_kernel(const __nv_bfloat16* __restrict__ Xh, const __nv_bfloat16* __restrict__ Xl,
                     const __nv_bfloat16* __restrict__ Wh, const __nv_bfloat16* __restrict__ Wl,
                     __nv_bfloat16* __restrict__ Yh, __nv_bfloat16* __restrict__ Yl,
                     int K, int Kpad)
{
    extern __shared__ char smem[];
    const uint32_t sb = s2u(smem);
    const int tid  = threadIdx.x;
    const int wid  = tid >> 5;
    const int lane = tid & 31;
    const int wm   = wid >> 2;
    const int wn   = wid & 3;
    const int n     = blockIdx.z;
    const int mBase = blockIdx.x * 128;
    const int nBase = blockIdx.y * 128;
    const int ldx   = N_LOCS * K;
    const bool fastK = (K == EMB);

    const __nv_bfloat16* Xhn = Xh + (size_t)n * K;
    const __nv_bfloat16* Xln = Xl + (size_t)n * K;
    const __nv_bfloat16* Whn = Wh + (size_t)n * EMB * Kpad;
    const __nv_bfloat16* Wln = Wl + (size_t)n * EMB * Kpad;

    float acc[4][4][4];
#pragma unroll
    for (int mt = 0; mt < 4; mt++)
#pragma unroll
        for (int nt = 0; nt < 4; nt++)
#pragma unroll
            for (int q = 0; q < 4; q++) acc[mt][nt][q] = 0.f;

    const int nchunk = Kpad >> 5;

    auto load_chunk = [&](int c) {
        const uint32_t st = sb + (c & 1) * STAGE_B;
        const int k0 = c << 5;
        if (fastK) {
#pragma unroll
            for (int it = 0; it < 2; it++) {
                int idx = tid + (it << 8);
                int r = idx >> 2, j = idx & 3;
                size_t go = (size_t)(mBase + r) * ldx + k0 + j * 8;
                uint32_t so = st + r * ROWB + j * 16;
                cp16(so,          Xhn + go);
                cp16(so + TILE_B, Xln + go);
            }
        } else {
            for (int it = 0; it < 16; it++) {
                int idx = tid + (it << 8);
                int r = idx >> 5, kk = idx & 31;
                int k = k0 + kk;
                __nv_bfloat16 vh = __float2bfloat16(0.f), vl = vh;
                if (k < K) {
                    size_t go = (size_t)(mBase + r) * ldx + k;
                    vh = Xhn[go]; vl = Xln[go];
                }
                uint32_t so = st + r * ROWB + kk * 2;
                *reinterpret_cast<__nv_bfloat16*>(smem + (so - sb))          = vh;
                *reinterpret_cast<__nv_bfloat16*>(smem + (so - sb) + TILE_B) = vl;
            }
        }
#pragma unroll
        for (int it = 0; it < 2; it++) {
            int idx = tid + (it << 8);
            int r = idx >> 2, j = idx & 3;
            size_t go = (size_t)(nBase + r) * Kpad + k0 + j * 8;
            uint32_t so = st + 2 * TILE_B + r * ROWB + j * 16;
            cp16(so,          Whn + go);
            cp16(so + TILE_B, Wln + go);
        }
        cp_commit();
    };

    load_chunk(0);

    for (int c = 0; c < nchunk; c++) {
        if (c + 1 < nchunk) { load_chunk(c + 1); cp_wait<1>(); }
        else                { cp_wait<0>(); }
        __syncthreads();

        const uint32_t st  = sb + (c & 1) * STAGE_B;
        const uint32_t sAh = st;
        const uint32_t sAl = st + TILE_B;
        const uint32_t sBh = st + 2 * TILE_B;
        const uint32_t sBl = st + 3 * TILE_B;

#pragma unroll
        for (int ks = 0; ks < 2; ks++) {
            uint32_t bh[4][2], bl[4][2];
            const uint32_t bOff = (wn * 32 + (lane & 7)) * ROWB
                                  + ks * 32 + ((lane >> 3) & 1) * 16;
#pragma unroll
            for (int nt = 0; nt < 4; nt++) {
                LDSM_X2(bh[nt][0], bh[nt][1], sBh + bOff + nt * 8 * ROWB);
                LDSM_X2(bl[nt][0], bl[nt][1], sBl + bOff + nt * 8 * ROWB);
            }
            const uint32_t aOff = (wm * 64 + (lane & 15)) * ROWB
                                  + ks * 32 + (lane >> 4) * 16;
#pragma unroll
            for (int mt = 0; mt < 4; mt++) {
                uint32_t ah[4], al[4];
                LDSM_X4(ah[0], ah[1], ah[2], ah[3], sAh + aOff + mt * 16 * ROWB);
                LDSM_X4(al[0], al[1], al[2], al[3], sAl + aOff + mt * 16 * ROWB);
#pragma unroll
                for (int nt = 0; nt < 4; nt++) {
                    MMA_BF16(acc[mt][nt], ah, bh[nt]);
                    MMA_BF16(acc[mt][nt], ah, bl[nt]);
                    MMA_BF16(acc[mt][nt], al, bh[nt]);
                }
            }
        }
        __syncthreads();
    }

    // epilogue: write Y as bf16 hi/lo, layout [b][n][o]
#pragma unroll
    for (int mt = 0; mt < 4; mt++) {
        int row0 = mBase + wm * 64 + mt * 16 + (lane >> 2);
#pragma unroll
        for (int nt = 0; nt < 4; nt++) {
            int col = nBase + wn * 32 + nt * 8 + 2 * (lane & 3);
            size_t o0 = ((size_t)row0 * N_LOCS + n) * EMB + col;
            size_t o1 = ((size_t)(row0 + 8) * N_LOCS + n) * EMB + col;
            float f0 = acc[mt][nt][0], f1 = acc[mt][nt][1];
            float f2 = acc[mt][nt][2], f3 = acc[mt][nt][3];
            float h0 = __bfloat162float(__float2bfloat16(f0));
            float h1 = __bfloat162float(__float2bfloat16(f1));
            float h2 = __bfloat162float(__float2bfloat16(f2));
            float h3 = __bfloat162float(__float2bfloat16(f3));
            *reinterpret_cast<uint32_t*>(Yh + o0) = pack2bf(f0, f1);
            *reinterpret_cast<uint32_t*>(Yl + o0) = pack2bf(f0 - h0, f1 - h1);
            *reinterpret_cast<uint32_t*>(Yh + o1) = pack2bf(f2, f3);
            *reinterpret_cast<uint32_t*>(Yl + o1) = pack2bf(f2 - h2, f3 - h3);
        }
    }
}

// ==================== stage 2: mix via HMMA  Z_b = A @ Y_b ===================
// CTA: one batch b, one o-half (128 cols). M=96 (81 real), K=96 (81 real).
#define MROWB 208
#define YROWB 272
#define MIX_SA   0
#define MIX_SAL  19968
#define MIX_SY   39936
#define MIX_SYL  66048
#define MIX_STAT 92160
#define MIX_SMEM 92928

__global__ __launch_bounds__(256, 2)
void mix_mma_kernel(const __nv_bfloat16* __restrict__ Yh, const __nv_bfloat16* __restrict__ Yl,
                    const float* __restrict__ bias, float* __restrict__ Z,
                    const __nv_bfloat16* __restrict__ Ahp, const __nv_bfloat16* __restrict__ Alp)
{
    extern __shared__ char smem[];
    const uint32_t sb = s2u(smem);
    const int tid = threadIdx.x, lane = tid & 31, wid = tid >> 5;
    const int wm = wid >> 2, wn = wid & 3;     // 2 x 4 warps: M 2x48, N 4x32
    const int b = blockIdx.x;
    const int oBase = blockIdx.y * 128;
    float* sS  = reinterpret_cast<float*>(smem + MIX_STAT);
    float* sSS = sS + 96;

    if (tid < 192) sS[tid] = 0.f;
    // zero Y pad rows 81..95
    for (int i = tid; i < 15 * 17; i += 256) {
        int r = 81 + i / 17, j = i % 17;
        uint4 zz = make_uint4(0, 0, 0, 0);
        *reinterpret_cast<uint4*>(smem + MIX_SY  + r * YROWB + j * 16) = zz;
        *reinterpret_cast<uint4*>(smem + MIX_SYL + r * YROWB + j * 16) = zz;
    }
    // load A hi/lo (96 x 96, row 192B = 12 x 16B)
    for (int i = tid; i < 1152; i += 256) {
        int r = i / 12, j = i % 12;
        cp16(sb + MIX_SA  + r * MROWB + j * 16, Ahp + r * 96 + j * 8);
        cp16(sb + MIX_SAL + r * MROWB + j * 16, Alp + r * 96 + j * 8);
    }
    // load Y hi/lo (81 rows x 128 o = 16 x 16B per row)
    for (int i = tid; i < 1296; i += 256) {
        int r = i / 16, j = i % 16;
        size_t go = ((size_t)b * N_LOCS + r) * EMB + oBase + j * 8;
        cp16(sb + MIX_SY  + r * YROWB + j * 16, Yh + go);
        cp16(sb + MIX_SYL + r * YROWB + j * 16, Yl + go);
    }
    cp_commit();
    cp_wait<0>();
    __syncthreads();

    float acc[3][4][4];
#pragma unroll
    for (int mt = 0; mt < 3; mt++)
#pragma unroll
        for (int nt = 0; nt < 4; nt++)
#pragma unroll
            for (int q = 0; q < 4; q++) acc[mt][nt][q] = 0.f;

#pragma unroll
    for (int ks = 0; ks < 6; ks++) {
        uint32_t bh[4][2], bl[4][2];
        const uint32_t yOff = (uint32_t)(ks * 16 + (lane & 15)) * YROWB + wn * 64;
#pragma unroll
        for (int nt = 0; nt < 4; nt++) {
            LDSM_X2T(bh[nt][0], bh[nt][1], sb + MIX_SY  + yOff + nt * 16);
            LDSM_X2T(bl[nt][0], bl[nt][1], sb + MIX_SYL + yOff + nt * 16);
        }
        const uint32_t aOff = (uint32_t)(wm * 48 + (lane & 15)) * MROWB
                              + ks * 32 + (lane >> 4) * 16;
#pragma unroll
        for (int mt = 0; mt < 3; mt++) {
            uint32_t ah[4], al[4];
            LDSM_X4(ah[0], ah[1], ah[2], ah[3], sb + MIX_SA  + aOff + mt * 16 * MROWB);
            LDSM_X4(al[0], al[1], al[2], al[3], sb + MIX_SAL + aOff + mt * 16 * MROWB);
#pragma unroll
            for (int nt = 0; nt < 4; nt++) {
                MMA_BF16(acc[mt][nt], ah, bh[nt]);
                MMA_BF16(acc[mt][nt], ah, bl[nt]);
                MMA_BF16(acc[mt][nt], al, bh[nt]);
            }
        }
    }

    // epilogue: +bias, store Z fp32, BN stats
    const float* bp = bias + oBase + wn * 32;
#pragma unroll
    for (int mt = 0; mt < 3; mt++) {
        int r0 = wm * 48 + mt * 16 + (lane >> 2);
        int r1 = r0 + 8;
        float s0 = 0.f, ss0 = 0.f, s1 = 0.f, ss1 = 0.f;
#pragma unroll
        for (int nt = 0; nt < 4; nt++) {
            int oc = nt * 8 + 2 * (lane & 3);
            float b0 = __ldg(bp + oc), b1 = __ldg(bp + oc + 1);
            float v0 = acc[mt][nt][0] + b0, v1 = acc[mt][nt][1] + b1;
            float v2 = acc[mt][nt][2] + b0, v3 = acc[mt][nt][3] + b1;
            int o = oBase + wn * 32 + oc;
            if (r0 < N_LOCS)
                *reinterpret_cast<float2*>(&Z[((size_t)b * N_LOCS + r0) * EMB + o]) =
                    make_float2(v0, v1);
            if (r1 < N_LOCS)
                *reinterpret_cast<float2*>(&Z[((size_t)b * N_LOCS + r1) * EMB + o]) =
                    make_float2(v2, v3);
            s0 += v0 + v1; ss0 += v0 * v0 + v1 * v1;
            s1 += v2 + v3; ss1 += v2 * v2 + v3 * v3;
        }
#pragma unroll
        for (int off = 1; off <= 2; off <<= 1) {
            s0  += __shfl_xor_sync(0xffffffffu, s0,  off);
            ss0 += __shfl_xor_sync(0xffffffffu, ss0, off);
            s1  += __shfl_xor_sync(0xffffffffu, s1,  off);
            ss1 += __shfl_xor_sync(0xffffffffu, ss1, off);
        }
        if ((lane & 3) == 0) {
            if (r0 < N_LOCS) { atomicAdd(&sS[r0], s0); atomicAdd(&sSS[r0], ss0); }
            if (r1 < N_LOCS) { atomicAdd(&sS[r1], s1); atomicAdd(&sSS[r1], ss1); }
        }
    }
    __syncthreads();
    for (int m = tid; m < N_LOCS; m += 256) {
        atomicAdd(&g_sum[m],   (double)sS[m]);
        atomicAdd(&g_sumsq[m], (double)sSS[m]);
    }
}

// ==================== stats fold ============================================
__global__ void stats_kernel(const float* __restrict__ g, const float* __restrict__ be)
{
    int m = threadIdx.x;
    if (m < N_LOCS) {
        const double cnt = (double)BATCH * (double)EMB;
        double mean = g_sum[m] / cnt;
        double var  = g_sumsq[m] / cnt - mean * mean;
        if (var < 0.0) var = 0.0;
        double inv = 1.0 / sqrt(var + 1e-5);
        float sc = g[m] * (float)inv;
        g_scale[m] = sc;
        g_shift[m] = be[m] - (float)mean * sc;
        g_sum[m] = 0.0; g_sumsq[m] = 0.0;
    }
}

// ==================== bn + relu (+ hi/lo residual) ==========================
__global__ __launch_bounds__(256)
void bn_relu_kernel(const float4* __restrict__ Z,
                    const __nv_bfloat16* __restrict__ Rh, const __nv_bfloat16* __restrict__ Rl,
                    float4* __restrict__ OutF,
                    __nv_bfloat16* __restrict__ Oh, __nv_bfloat16* __restrict__ Ol,
                    int sB4, int sM4)
{
    int i  = blockIdx.x * 256 + threadIdx.x;
    int o4 = i & 63, t = i >> 6;
    int bb = t / N_LOCS, m = t - bb * N_LOCS;
    float sc = g_scale[m], sh = g_shift[m];
    float4 z = Z[i];
    float4 o;
    o.x = fmaxf(fmaf(z.x, sc, sh), 0.f);
    o.y = fmaxf(fmaf(z.y, sc, sh), 0.f);
    o.z = fmaxf(fmaf(z.z, sc, sh), 0.f);
    o.w = fmaxf(fmaf(z.w, sc, sh), 0.f);
    if (Rh != nullptr) {
        uint2 RH = reinterpret_cast<const uint2*>(Rh)[i];
        uint2 RL = reinterpret_cast<const uint2*>(Rl)[i];
        __nv_bfloat162 h0 = *reinterpret_cast<__nv_bfloat162*>(&RH.x);
        __nv_bfloat162 h1 = *reinterpret_cast<__nv_bfloat162*>(&RH.y);
        __nv_bfloat162 l0 = *reinterpret_cast<__nv_bfloat162*>(&RL.x);
        __nv_bfloat162 l1 = *reinterpret_cast<__nv_bfloat162*>(&RL.y);
        o.x += __bfloat162float(h0.x) + __bfloat162float(l0.x);
        o.y += __bfloat162float(h0.y) + __bfloat162float(l0.y);
        o.z += __bfloat162float(h1.x) + __bfloat162float(l1.x);
        o.w += __bfloat162float(h1.y) + __bfloat162float(l1.y);
    }
    if (OutF != nullptr) {
        OutF[(size_t)bb * sB4 + (size_t)m * sM4 + o4] = o;
    } else {
        float hx = __bfloat162float(__float2bfloat16(o.x));
        float hy = __bfloat162float(__float2bfloat16(o.y));
        float hz = __bfloat162float(__float2bfloat16(o.z));
        float hw = __bfloat162float(__float2bfloat16(o.w));
        uint2 H, L;
        H.x = pack2bf(o.x, o.y); H.y = pack2bf(o.z, o.w);
        L.x = pack2bf(o.x - hx, o.y - hy); L.y = pack2bf(o.z - hz, o.w - hw);
        reinterpret_cast<uint2*>(Oh)[i] = H;
        reinterpret_cast<uint2*>(Ol)[i] = L;
    }
}

// ==================== weight transpose + split ==============================
__global__ void tconv_kernel(const float* __restrict__ W,
                             __nv_bfloat16* __restrict__ oh, __nv_bfloat16* __restrict__ ol,
                             int K, int Kpad)
{
    __shared__ float t[32][33];
    int nm = blockIdx.x, ob = blockIdx.y * 32, kb = blockIdx.z * 32;
    const float* Wn = W + (size_t)nm * K * EMB;
    for (int r = threadIdx.y; r < 32; r += 8) {
        int k = kb + r;
        t[r][threadIdx.x] = (k < K) ? Wn[(size_t)k * EMB + ob + threadIdx.x] : 0.f;
    }
    __syncthreads();
    size_t obase = (size_t)nm * EMB * Kpad;
    for (int r = threadIdx.y; r < 32; r += 8) {
        float v = t[threadIdx.x][r];
        __nv_bfloat16 h = __float2bfloat16(v);
        size_t d = obase + (size_t)(ob + r) * Kpad + kb + threadIdx.x;
        oh[d] = h;
        ol[d] = __float2bfloat16(v - __bfloat162float(h));
    }
}

__global__ void split_kernel(const float* __restrict__ x,
                             __nv_bfloat16* __restrict__ h, __nv_bfloat16* __restrict__ l, int n)
{
    int i = blockIdx.x * 256 + threadIdx.x;
    if (i < n) {
        float v = x[i];
        __nv_bfloat16 hh = __float2bfloat16(v);
        h[i] = hh;
        l[i] = __float2bfloat16(v - __bfloat162float(hh));
    }
}

__global__ void asplit_kernel(const float* __restrict__ A,
                              __nv_bfloat16* __restrict__ Ah, __nv_bfloat16* __restrict__ Al)
{
    int i = blockIdx.x * 256 + threadIdx.x;
    if (i < 96 * 96) {
        int m = i / 96, nn = i % 96;
        float v = (m < N_LOCS && nn < N_LOCS) ? A[m * N_LOCS + nn] : 0.f;
        __nv_bfloat16 h = __float2bfloat16(v);
        Ah[i] = h;
        Al[i] = __float2bfloat16(v - __bfloat162float(h));
    }
}

// ==================== host orchestration ====================================
static void run_stack(const float* x, int K0,
                      const float* W0, const float* b0, const float* g0, const float* be0,
                      const float* Ws, const float* bs, const float* gs, const float* bes,
                      float* bufZ, __nv_bfloat16* yh, __nv_bfloat16* yl,
                      __nv_bfloat16* ah0, __nv_bfloat16* al0,
                      __nv_bfloat16* ah1, __nv_bfloat16* al1,
                      __nv_bfloat16* wth, __nv_bfloat16* wtl,
                      __nv_bfloat16* w0h, __nv_bfloat16* w0l,
                      __nv_bfloat16* Ah96, __nv_bfloat16* Al96, float* outF)
{
    dim3 tcb(32, 8);
    tconv_kernel<<<dim3(N_LOCS, 8, 2), tcb>>>(W0, w0h, w0l, K0, 64);
    tconv_kernel<<<dim3(7 * N_LOCS, 8, 8), tcb>>>(Ws, wth, wtl, EMB, EMB);
    int nx = BATCH * N_LOCS * K0;
    split_kernel<<<(nx + 255) / 256, 256>>>(x, ah0, al0, nx);

    const dim3 gG(BATCH / 128, EMB / 128, N_LOCS);
    const dim3 gMix(BATCH, 2);
    const int  gNorm = ELEMS / 4 / 256;
    __nv_bfloat16* AH[2] = { ah0, ah1 };
    __nv_bfloat16* AL[2] = { al0, al1 };

    gemm_mma_kernel<<<gG, 256, GEMM_SMEM>>>(ah0, al0, w0h, w0l, yh, yl, K0, 64);
    mix_mma_kernel<<<gMix, 256, MIX_SMEM>>>(yh, yl, b0, bufZ, Ah96, Al96);
    stats_kernel<<<1, N_LOCS>>>(g0, be0);
    bn_relu_kernel<<<gNorm, 256>>>((const float4*)bufZ, nullptr, nullptr,
                                   nullptr, ah1, al1, 0, 0);
    for (int bi = 1; bi <= 7; bi++) {
        int i = bi - 1, r = bi & 1, w = (bi + 1) & 1;
        gemm_mma_kernel<<<gG, 256, GEMM_SMEM>>>(
            AH[r], AL[r],
            wth + (size_t)i * N_LOCS * EMB * EMB, wtl + (size_t)i * N_LOCS * EMB * EMB,
            yh, yl, EMB, EMB);
        mix_mma_kernel<<<gMix, 256, MIX_SMEM>>>(yh, yl, bs + (size_t)i * EMB, bufZ,
                                                Ah96, Al96);
        stats_kernel<<<1, N_LOCS>>>(gs + (size_t)i * N_LOCS, bes + (size_t)i * N_LOCS);
        if (bi == 7)
            bn_relu_kernel<<<gNorm, 256>>>((const float4*)bufZ, AH[r], AL[r],
                                           (float4*)outF, nullptr, nullptr,
                                           N_LOCS * 128, 128);
        else
            bn_relu_kernel<<<gNorm, 256>>>((const float4*)bufZ, AH[r], AL[r],
                                           nullptr, AH[w], AL[w], 0, 0);
    }
}

extern "C" void kernel_launch(void* const* d_in, const int* in_sizes, int n_in,
                              void* d_out, int out_size)
{
    (void)in_sizes; (void)n_in; (void)out_size;
    const float* x_bo   = (const float*)d_in[0];
    const float* x_po   = (const float*)d_in[1];
    const float* A      = (const float*)d_in[2];
    const float* W0_bo  = (const float*)d_in[3];
    const float* b0_bo  = (const float*)d_in[4];
    const float* g0_bo  = (const float*)d_in[5];
    const float* be0_bo = (const float*)d_in[6];
    const float* W_bo   = (const float*)d_in[7];
    const float* b_bo   = (const float*)d_in[8];
    const float* g_bo   = (const float*)d_in[9];
    const float* be_bo  = (const float*)d_in[10];
    const float* W0_po  = (const float*)d_in[11];
    const float* b0_po  = (const float*)d_in[12];
    const float* g0_po  = (const float*)d_in[13];
    const float* be0_po = (const float*)d_in[14];
    const float* W_po   = (const float*)d_in[15];
    const float* b_po   = (const float*)d_in[16];
    const float* g_po   = (const float*)d_in[17];
    const float* be_po  = (const float*)d_in[18];
    float* out = (float*)d_out;

    cudaFuncSetAttribute(gemm_mma_kernel,
                         cudaFuncAttributeMaxDynamicSharedMemorySize, GEMM_SMEM);
    cudaFuncSetAttribute(mix_mma_kernel,
                         cudaFuncAttributeMaxDynamicSharedMemorySize, MIX_SMEM);

    float *bufZ;
    __nv_bfloat16 *yh, *yl, *ah0, *al0, *ah1, *al1, *wth, *wtl, *w0h, *w0l, *Ah96, *Al96;
    cudaGetSymbolAddress((void**)&bufZ, g_bufB);
    cudaGetSymbolAddress((void**)&yh, g_yh);
    cudaGetSymbolAddress((void**)&yl, g_yl);
    cudaGetSymbolAddress((void**)&ah0, g_ah0);
    cudaGetSymbolAddress((void**)&al0, g_al0);
    cudaGetSymbolAddress((void**)&ah1, g_ah1);
    cudaGetSymbolAddress((void**)&al1, g_al1);
    cudaGetSymbolAddress((void**)&wth, g_wth);
    cudaGetSymbolAddress((void**)&wtl, g_wtl);
    cudaGetSymbolAddress((void**)&w0h, g_w0h);
    cudaGetSymbolAddress((void**)&w0l, g_w0l);
    cudaGetSymbolAddress((void**)&Ah96, g_Ah96);
    cudaGetSymbolAddress((void**)&Al96, g_Al96);

    asplit_kernel<<<36, 256>>>(A, Ah96, Al96);

    run_stack(x_bo, 35, W0_bo, b0_bo, g0_bo, be0_bo, W_bo, b_bo, g_bo, be_bo,
              bufZ, yh, yl, ah0, al0, ah1, al1, wth, wtl, w0h, w0l, Ah96, Al96, out);
    run_stack(x_po, 40, W0_po, b0_po, g0_po, be0_po, W_po, b_po, g_po, be_po,
              bufZ, yh, yl, ah0, al0, ah1, al1, wth, wtl, w0h, w0l, Ah96, Al96, out + EMB);
}

// round 7
// speedup vs baseline: 1.9119x; 1.0194x over previous
#include <cuda_runtime.h>
#include <cuda_bf16.h>
#include <cstdint>
#include <cstddef>

#define N_LOCS 81
#define BATCH  2048
#define EMB    256
#define ELEMS  (BATCH * N_LOCS * EMB)
#define WS_ELEMS (7 * N_LOCS * EMB * EMB)
#define W0_ELEMS (N_LOCS * EMB * 64)

__device__ float  g_bufZ[ELEMS];                 // Z (mix output, fp32)
__device__ __nv_bfloat16 g_yh[ELEMS];            // Y hi/lo (gemm output)
__device__ __nv_bfloat16 g_yl[ELEMS];
__device__ __nv_bfloat16 g_ah0[ELEMS];           // activation ping-pong hi/lo
__device__ __nv_bfloat16 g_al0[ELEMS];
__device__ __nv_bfloat16 g_ah1[ELEMS];
__device__ __nv_bfloat16 g_al1[ELEMS];
__device__ __nv_bfloat16 g_wth[WS_ELEMS];
__device__ __nv_bfloat16 g_wtl[WS_ELEMS];
__device__ __nv_bfloat16 g_w0h[W0_ELEMS];
__device__ __nv_bfloat16 g_w0l[W0_ELEMS];
__device__ __nv_bfloat16 g_Ah96[96 * 96];
__device__ __nv_bfloat16 g_Al96[96 * 96];
__device__ double g_sum[N_LOCS];
__device__ double g_sumsq[N_LOCS];
__device__ float  g_scale[N_LOCS];
__device__ float  g_shift[N_LOCS];

__device__ __forceinline__ uint32_t s2u(const void* p) {
    uint32_t a;
    asm("{ .reg .u64 t; cvta.to.shared.u64 t, %1; cvt.u32.u64 %0, t; }" : "=r"(a) : "l"(p));
    return a;
}
__device__ __forceinline__ void cp16(uint32_t s, const void* g) {
    asm volatile("cp.async.cg.shared.global [%0], [%1], 16;" :: "r"(s), "l"(g) : "memory");
}
__device__ __forceinline__ void cp_commit() {
    asm volatile("cp.async.commit_group;" ::: "memory");
}
template <int N>
__device__ __forceinline__ void cp_wait() {
    asm volatile("cp.async.wait_group %0;" :: "n"(N) : "memory");
}
#define LDSM_X4(r0, r1, r2, r3, addr) \
    asm volatile("ldmatrix.sync.aligned.m8n8.x4.shared.b16 {%0,%1,%2,%3}, [%4];" \
                 : "=r"(r0), "=r"(r1), "=r"(r2), "=r"(r3) : "r"(addr))
#define LDSM_X2(r0, r1, addr) \
    asm volatile("ldmatrix.sync.aligned.m8n8.x2.shared.b16 {%0,%1}, [%2];" \
                 : "=r"(r0), "=r"(r1) : "r"(addr))
#define LDSM_X2T(r0, r1, addr) \
    asm volatile("ldmatrix.sync.aligned.m8n8.x2.trans.shared.b16 {%0,%1}, [%2];" \
                 : "=r"(r0), "=r"(r1) : "r"(addr))
#define MMA_BF16(d, a, b) \
    asm volatile("mma.sync.aligned.m16n8k16.row.col.f32.bf16.bf16.f32 " \
                 "{%0,%1,%2,%3}, {%4,%5,%6,%7}, {%8,%9}, {%0,%1,%2,%3};" \
                 : "+f"((d)[0]), "+f"((d)[1]), "+f"((d)[2]), "+f"((d)[3]) \
                 : "r"((a)[0]), "r"((a)[1]), "r"((a)[2]), "r"((a)[3]), \
                   "r"((b)[0]), "r"((b)[1]))

__device__ __forceinline__ uint32_t pack2bf(float a, float b) {
    __nv_bfloat162 t;
    t.x = __float2bfloat16(a); t.y = __float2bfloat16(b);
    return *reinterpret_cast<uint32_t*>(&t);
}

#define ROWB   80
#define TILE_B 10240
#define STAGE_B 40960
#define GEMM_SMEM (2 * STAGE_B)

// =================== MMA core (shared by both gemm kernels) ==================
struct GemmCtx {
    uint32_t sb;
    int tid, wid, lane, wm, wn;
};

__device__ __forceinline__ void gemm_compute_stage(const GemmCtx& g, int c,
                                                   float acc[4][4][4])
{
    const uint32_t st  = g.sb + (c & 1) * STAGE_B;
    const uint32_t sAh = st;
    const uint32_t sAl = st + TILE_B;
    const uint32_t sBh = st + 2 * TILE_B;
    const uint32_t sBl = st + 3 * TILE_B;
#pragma unroll
    for (int ks = 0; ks < 2; ks++) {
        uint32_t bh[4][2], bl[4][2];
        const uint32_t bOff = (g.wn * 32 + (g.lane & 7)) * ROWB
                              + ks * 32 + ((g.lane >> 3) & 1) * 16;
#pragma unroll
        for (int nt = 0; nt < 4; nt++) {
            LDSM_X2(bh[nt][0], bh[nt][1], sBh + bOff + nt * 8 * ROWB);
            LDSM_X2(bl[nt][0], bl[nt][1], sBl + bOff + nt * 8 * ROWB);
        }
        const uint32_t aOff = (g.wm * 64 + (g.lane & 15)) * ROWB
                              + ks * 32 + (g.lane >> 4) * 16;
#pragma unroll
        for (int mt = 0; mt < 4; mt++) {
            uint32_t ah[4], al[4];
            LDSM_X4(ah[0], ah[1], ah[2], ah[3], sAh + aOff + mt * 16 * ROWB);
            LDSM_X4(al[0], al[1], al[2], al[3], sAl + aOff + mt * 16 * ROWB);
#pragma unroll
            for (int nt = 0; nt < 4; nt++) {
                MMA_BF16(acc[mt][nt], ah, bh[nt]);
                MMA_BF16(acc[mt][nt], ah, bl[nt]);
                MMA_BF16(acc[mt][nt], al, bh[nt]);
            }
        }
    }
}

__device__ __forceinline__ void gemm_epilogue(const GemmCtx& g, float acc[4][4][4],
                                              int mBase, int nBase, int n,
                                              __nv_bfloat16* Yh, __nv_bfloat16* Yl)
{
#pragma unroll
    for (int mt = 0; mt < 4; mt++) {
        int row0 = mBase + g.wm * 64 + mt * 16 + (g.lane >> 2);
#pragma unroll
        for (int nt = 0; nt < 4; nt++) {
            int col = nBase + g.wn * 32 + nt * 8 + 2 * (g.lane & 3);
            size_t o0 = ((size_t)row0 * N_LOCS + n) * EMB + col;
            size_t o1 = ((size_t)(row0 + 8) * N_LOCS + n) * EMB + col;
            float f0 = acc[mt][nt][0], f1 = acc[mt][nt][1];
            float f2 = acc[mt][nt][2], f3 = acc[mt][nt][3];
            float h0 = __bfloat162float(__float2bfloat16(f0));
            float h1 = __bfloat162float(__float2bfloat16(f1));
            float h2 = __bfloat162float(__float2bfloat16(f2));
            float h3 = __bfloat162float(__float2bfloat16(f3));
            *reinterpret_cast<uint32_t*>(Yh + o0) = pack2bf(f0, f1);
            *reinterpret_cast<uint32_t*>(Yl + o0) = pack2bf(f0 - h0, f1 - h1);
            *reinterpret_cast<uint32_t*>(Yh + o1) = pack2bf(f2, f3);
            *reinterpret_cast<uint32_t*>(Yl + o1) = pack2bf(f2 - h2, f3 - h3);
        }
    }
}

// ============ stage 1a: block-0 GEMM (raw fp32 x, split in-register) =========
__global__ __launch_bounds__(256, 2)
void gemm0_kernel(const float* __restrict__ X,
                  const __nv_bfloat16* __restrict__ Wh, const __nv_bfloat16* __restrict__ Wl,
                  __nv_bfloat16* __restrict__ Yh, __nv_bfloat16* __restrict__ Yl,
                  int K, int Kpad)
{
    extern __shared__ char smem[];
    GemmCtx g;
    g.sb = s2u(smem); g.tid = threadIdx.x; g.wid = g.tid >> 5; g.lane = g.tid & 31;
    g.wm = g.wid >> 2; g.wn = g.wid & 3;
    const int n = blockIdx.z, mBase = blockIdx.x * 128, nBase = blockIdx.y * 128;
    const int ldx = N_LOCS * K;
    const float* Xn = X + (size_t)n * K;
    const __nv_bfloat16* Whn = Wh + (size_t)n * EMB * Kpad;
    const __nv_bfloat16* Wln = Wl + (size_t)n * EMB * Kpad;

    float acc[4][4][4];
#pragma unroll
    for (int mt = 0; mt < 4; mt++)
#pragma unroll
        for (int nt = 0; nt < 4; nt++)
#pragma unroll
            for (int q = 0; q < 4; q++) acc[mt][nt][q] = 0.f;

    const int nchunk = Kpad >> 5;

    auto load_chunk = [&](int c) {
        const uint32_t stOff = (c & 1) * STAGE_B;
        const int k0 = c << 5;
        for (int it = 0; it < 16; it++) {
            int idx = g.tid + (it << 8);
            int r = idx >> 5, kk = idx & 31;
            int k = k0 + kk;
            float v = (k < K) ? Xn[(size_t)(mBase + r) * ldx + k] : 0.f;
            float h = __bfloat162float(__float2bfloat16(v));
            uint32_t so = stOff + r * ROWB + kk * 2;
            *reinterpret_cast<__nv_bfloat16*>(smem + so)          = __float2bfloat16(v);
            *reinterpret_cast<__nv_bfloat16*>(smem + so + TILE_B) = __float2bfloat16(v - h);
        }
#pragma unroll
        for (int it = 0; it < 2; it++) {
            int idx = g.tid + (it << 8);
            int r = idx >> 2, j = idx & 3;
            size_t go = (size_t)(nBase + r) * Kpad + k0 + j * 8;   // FIX: +nBase
            uint32_t so = g.sb + stOff + 2 * TILE_B + r * ROWB + j * 16;
            cp16(so,          Whn + go);
            cp16(so + TILE_B, Wln + go);
        }
        cp_commit();
    };

    load_chunk(0);
    for (int c = 0; c < nchunk; c++) {
        if (c + 1 < nchunk) { load_chunk(c + 1); cp_wait<1>(); }
        else                { cp_wait<0>(); }
        __syncthreads();
        gemm_compute_stage(g, c, acc);
        __syncthreads();
    }
    gemm_epilogue(g, acc, mBase, nBase, n, Yh, Yl);
}

// ===== stage 1b: fused GEMM — bn+relu+residual+split applied in loader =======
__global__ __launch_bounds__(256, 2)
void gemm_fused_kernel(const float* __restrict__ Zin,
                       const __nv_bfloat16* __restrict__ Rh, const __nv_bfloat16* __restrict__ Rl,
                       __nv_bfloat16* __restrict__ Oh, __nv_bfloat16* __restrict__ Ol,
                       const __nv_bfloat16* __restrict__ Wh, const __nv_bfloat16* __restrict__ Wl,
                       __nv_bfloat16* __restrict__ Yh, __nv_bfloat16* __restrict__ Yl)
{
    extern __shared__ char smem[];
    GemmCtx g;
    g.sb = s2u(smem); g.tid = threadIdx.x; g.wid = g.tid >> 5; g.lane = g.tid & 31;
    g.wm = g.wid >> 2; g.wn = g.wid & 3;
    const int n = blockIdx.z, mBase = blockIdx.x * 128, nBase = blockIdx.y * 128;
    const __nv_bfloat16* Whn = Wh + (size_t)n * EMB * EMB;
    const __nv_bfloat16* Wln = Wl + (size_t)n * EMB * EMB;
    const float sc = g_scale[n], sh = g_shift[n];
    const bool hasRes = (Rh != nullptr);
    const bool writeO = (blockIdx.y == 0);

    float acc[4][4][4];
#pragma unroll
    for (int mt = 0; mt < 4; mt++)
#pragma unroll
        for (int nt = 0; nt < 4; nt++)
#pragma unroll
            for (int q = 0; q < 4; q++) acc[mt][nt][q] = 0.f;

    auto load_chunk = [&](int c) {
        const uint32_t stOff = (c & 1) * STAGE_B;
        const int k0 = c << 5;
#pragma unroll
        for (int it = 0; it < 4; it++) {
            int idx = g.tid + (it << 8);
            int r = idx >> 3, j = idx & 7;
            size_t go = ((size_t)(mBase + r) * N_LOCS + n) * EMB + k0 + j * 4;
            float4 z = *reinterpret_cast<const float4*>(Zin + go);
            float4 o;
            o.x = fmaxf(fmaf(z.x, sc, sh), 0.f);
            o.y = fmaxf(fmaf(z.y, sc, sh), 0.f);
            o.z = fmaxf(fmaf(z.z, sc, sh), 0.f);
            o.w = fmaxf(fmaf(z.w, sc, sh), 0.f);
            if (hasRes) {
                uint2 RH2 = *reinterpret_cast<const uint2*>(Rh + go);
                uint2 RL2 = *reinterpret_cast<const uint2*>(Rl + go);
                __nv_bfloat162 h0 = *reinterpret_cast<__nv_bfloat162*>(&RH2.x);
                __nv_bfloat162 h1 = *reinterpret_cast<__nv_bfloat162*>(&RH2.y);
                __nv_bfloat162 l0 = *reinterpret_cast<__nv_bfloat162*>(&RL2.x);
                __nv_bfloat162 l1 = *reinterpret_cast<__nv_bfloat162*>(&RL2.y);
                o.x += __bfloat162float(h0.x) + __bfloat162float(l0.x);
                o.y += __bfloat162float(h0.y) + __bfloat162float(l0.y);
                o.z += __bfloat162float(h1.x) + __bfloat162float(l1.x);
                o.w += __bfloat162float(h1.y) + __bfloat162float(l1.y);
            }
            float hx = __bfloat162float(__float2bfloat16(o.x));
            float hy = __bfloat162float(__float2bfloat16(o.y));
            float hz = __bfloat162float(__float2bfloat16(o.z));
            float hw = __bfloat162float(__float2bfloat16(o.w));
            uint2 H = make_uint2(pack2bf(o.x, o.y), pack2bf(o.z, o.w));
            uint2 L = make_uint2(pack2bf(o.x - hx, o.y - hy), pack2bf(o.z - hz, o.w - hw));
            uint32_t so = stOff + r * ROWB + j * 8;
            *reinterpret_cast<uint2*>(smem + so)          = H;
            *reinterpret_cast<uint2*>(smem + so + TILE_B) = L;
            if (writeO) {
                *reinterpret_cast<uint2*>(Oh + go) = H;
                *reinterpret_cast<uint2*>(Ol + go) = L;
            }
        }
#pragma unroll
        for (int it = 0; it < 2; it++) {
            int idx = g.tid + (it << 8);
            int r = idx >> 2, j = idx & 3;
            size_t go = (size_t)(nBase + r) * EMB + k0 + j * 8;    // FIX: +nBase
            uint32_t so = g.sb + stOff + 2 * TILE_B + r * ROWB + j * 16;
            cp16(so,          Whn + go);
            cp16(so + TILE_B, Wln + go);
        }
        cp_commit();
    };

    load_chunk(0);
#pragma unroll 1
    for (int c = 0; c < 8; c++) {
        if (c + 1 < 8) { load_chunk(c + 1); cp_wait<1>(); }
        else           { cp_wait<0>(); }
        __syncthreads();
        gemm_compute_stage(g, c, acc);
        __syncthreads();
    }
    gemm_epilogue(g, acc, mBase, nBase, n, Yh, Yl);
}

// ==================== stage 2: mix via HMMA  Z_b = A @ Y_b ===================
#define BPC 4
#define MROWB 208
#define YROWB 272
#define MIX_SA   0
#define MIX_SAL  19968
#define MIX_SY   39936
#define MIX_SYL  66048
#define MIX_STAT 92160
#define MIX_SMEM 92928

__global__ __launch_bounds__(256, 2)
void mix_mma_kernel(const __nv_bfloat16* __restrict__ Yh, const __nv_bfloat16* __restrict__ Yl,
                    const float* __restrict__ bias, float* __restrict__ Z,
                    const __nv_bfloat16* __restrict__ Ahp, const __nv_bfloat16* __restrict__ Alp)
{
    extern __shared__ char smem[];
    const uint32_t sb = s2u(smem);
    const int tid = threadIdx.x, lane = tid & 31, wid = tid >> 5;
    const int wm = wid >> 2, wn = wid & 3;
    const int b0 = blockIdx.x * BPC;
    const int oBase = blockIdx.y * 128;
    float* sS  = reinterpret_cast<float*>(smem + MIX_STAT);
    float* sSS = sS + 96;

    if (tid < 192) sS[tid] = 0.f;
    for (int i = tid; i < 15 * 17; i += 256) {
        int r = 81 + i / 17, j = i % 17;
        uint4 zz = make_uint4(0, 0, 0, 0);
        *reinterpret_cast<uint4*>(smem + MIX_SY  + r * YROWB + j * 16) = zz;
        *reinterpret_cast<uint4*>(smem + MIX_SYL + r * YROWB + j * 16) = zz;
    }
    for (int i = tid; i < 1152; i += 256) {
        int r = i / 12, j = i % 12;
        cp16(sb + MIX_SA  + r * MROWB + j * 16, Ahp + r * 96 + j * 8);
        cp16(sb + MIX_SAL + r * MROWB + j * 16, Alp + r * 96 + j * 8);
    }
    for (int i = tid; i < 1296; i += 256) {
        int r = i / 16, j = i % 16;
        size_t go = ((size_t)b0 * N_LOCS + r) * EMB + oBase + j * 8;
        cp16(sb + MIX_SY  + r * YROWB + j * 16, Yh + go);
        cp16(sb + MIX_SYL + r * YROWB + j * 16, Yl + go);
    }
    cp_commit();
    cp_wait<0>();
    __syncthreads();

    for (int bb = 0; bb < BPC; bb++) {
        const int b = b0 + bb;
        if (bb > 0) {
            __syncthreads();
            for (int i = tid; i < 1296; i += 256) {
                int r = i / 16, j = i % 16;
                size_t go = ((size_t)b * N_LOCS + r) * EMB + oBase + j * 8;
                cp16(sb + MIX_SY  + r * YROWB + j * 16, Yh + go);
                cp16(sb + MIX_SYL + r * YROWB + j * 16, Yl + go);
            }
            cp_commit();
            cp_wait<0>();
            __syncthreads();
        }

        float acc[3][4][4];
#pragma unroll
        for (int mt = 0; mt < 3; mt++)
#pragma unroll
            for (int nt = 0; nt < 4; nt++)
#pragma unroll
                for (int q = 0; q < 4; q++) acc[mt][nt][q] = 0.f;

#pragma unroll
        for (int ks = 0; ks < 6; ks++) {
            uint32_t bh[4][2], bl[4][2];
            const uint32_t yOff = (uint32_t)(ks * 16 + (lane & 15)) * YROWB + wn * 64;
#pragma unroll
            for (int nt = 0; nt < 4; nt++) {
                LDSM_X2T(bh[nt][0], bh[nt][1], sb + MIX_SY  + yOff + nt * 16);
                LDSM_X2T(bl[nt][0], bl[nt][1], sb + MIX_SYL + yOff + nt * 16);
            }
            const uint32_t aOff = (uint32_t)(wm * 48 + (lane & 15)) * MROWB
                                  + ks * 32 + (lane >> 4) * 16;
#pragma unroll
            for (int mt = 0; mt < 3; mt++) {
                uint32_t ah[4], al[4];
                LDSM_X4(ah[0], ah[1], ah[2], ah[3], sb + MIX_SA  + aOff + mt * 16 * MROWB);
                LDSM_X4(al[0], al[1], al[2], al[3], sb + MIX_SAL + aOff + mt * 16 * MROWB);
#pragma unroll
                for (int nt = 0; nt < 4; nt++) {
                    MMA_BF16(acc[mt][nt], ah, bh[nt]);
                    MMA_BF16(acc[mt][nt], ah, bl[nt]);
                    MMA_BF16(acc[mt][nt], al, bh[nt]);
                }
            }
        }

        const float* bp = bias + oBase + wn * 32;
#pragma unroll
        for (int mt = 0; mt < 3; mt++) {
            int r0 = wm * 48 + mt * 16 + (lane >> 2);
            int r1 = r0 + 8;
            float s0 = 0.f, ss0 = 0.f, s1 = 0.f, ss1 = 0.f;
#pragma unroll
            for (int nt = 0; nt < 4; nt++) {
                int oc = nt * 8 + 2 * (lane & 3);
                float bb0 = __ldg(bp + oc), bb1 = __ldg(bp + oc + 1);
                float v0 = acc[mt][nt][0] + bb0, v1 = acc[mt][nt][1] + bb1;
                float v2 = acc[mt][nt][2] + bb0, v3 = acc[mt][nt][3] + bb1;
                int o = oBase + wn * 32 + oc;
                if (r0 < N_LOCS)
                    *reinterpret_cast<float2*>(&Z[((size_t)b * N_LOCS + r0) * EMB + o]) =
                        make_float2(v0, v1);
                if (r1 < N_LOCS)
                    *reinterpret_cast<float2*>(&Z[((size_t)b * N_LOCS + r1) * EMB + o]) =
                        make_float2(v2, v3);
                s0 += v0 + v1; ss0 += v0 * v0 + v1 * v1;
                s1 += v2 + v3; ss1 += v2 * v2 + v3 * v3;
            }
#pragma unroll
            for (int off = 1; off <= 2; off <<= 1) {
                s0  += __shfl_xor_sync(0xffffffffu, s0,  off);
                ss0 += __shfl_xor_sync(0xffffffffu, ss0, off);
                s1  += __shfl_xor_sync(0xffffffffu, s1,  off);
                ss1 += __shfl_xor_sync(0xffffffffu, ss1, off);
            }
            if ((lane & 3) == 0) {
                if (r0 < N_LOCS) { atomicAdd(&sS[r0], s0); atomicAdd(&sSS[r0], ss0); }
                if (r1 < N_LOCS) { atomicAdd(&sS[r1], s1); atomicAdd(&sSS[r1], ss1); }
            }
        }
    }
    __syncthreads();
    for (int m = tid; m < N_LOCS; m += 256) {
        atomicAdd(&g_sum[m],   (double)sS[m]);
        atomicAdd(&g_sumsq[m], (double)sSS[m]);
    }
}

// ==================== stats fold =============================================
__global__ void stats_kernel(const float* __restrict__ g, const float* __restrict__ be)
{
    int m = threadIdx.x;
    if (m < N_LOCS) {
        const double cnt = (double)BATCH * (double)EMB;
        double mean = g_sum[m] / cnt;
        double var  = g_sumsq[m] / cnt - mean * mean;
        if (var < 0.0) var = 0.0;
        double inv = 1.0 / sqrt(var + 1e-5);
        float sc = g[m] * (float)inv;
        g_scale[m] = sc;
        g_shift[m] = be[m] - (float)mean * sc;
        g_sum[m] = 0.0; g_sumsq[m] = 0.0;
    }
}

// ============ final bn + relu + residual -> strided fp32 output ==============
__global__ __launch_bounds__(256)
void bn_final_kernel(const float4* __restrict__ Z,
                     const __nv_bfloat16* __restrict__ Rh, const __nv_bfloat16* __restrict__ Rl,
                     float4* __restrict__ OutF)
{
    int i  = blockIdx.x * 256 + threadIdx.x;
    int o4 = i & 63, t = i >> 6;
    int bb = t / N_LOCS, m = t - bb * N_LOCS;
    float sc = g_scale[m], sh = g_shift[m];
    float4 z = Z[i];
    float4 o;
    o.x = fmaxf(fmaf(z.x, sc, sh), 0.f);
    o.y = fmaxf(fmaf(z.y, sc, sh), 0.f);
    o.z = fmaxf(fmaf(z.z, sc, sh), 0.f);
    o.w = fmaxf(fmaf(z.w, sc, sh), 0.f);
    uint2 RH = reinterpret_cast<const uint2*>(Rh)[i];
    uint2 RL = reinterpret_cast<const uint2*>(Rl)[i];
    __nv_bfloat162 h0 = *reinterpret_cast<__nv_bfloat162*>(&RH.x);
    __nv_bfloat162 h1 = *reinterpret_cast<__nv_bfloat162*>(&RH.y);
    __nv_bfloat162 l0 = *reinterpret_cast<__nv_bfloat162*>(&RL.x);
    __nv_bfloat162 l1 = *reinterpret_cast<__nv_bfloat162*>(&RL.y);
    o.x += __bfloat162float(h0.x) + __bfloat162float(l0.x);
    o.y += __bfloat162float(h0.y) + __bfloat162float(l0.y);
    o.z += __bfloat162float(h1.x) + __bfloat162float(l1.x);
    o.w += __bfloat162float(h1.y) + __bfloat162float(l1.y);
    OutF[(size_t)bb * (N_LOCS * 128) + (size_t)m * 128 + o4] = o;
}

// ==================== weight transpose + split ===============================
__global__ void tconv_kernel(const float* __restrict__ W,
                             __nv_bfloat16* __restrict__ oh, __nv_bfloat16* __restrict__ ol,
                             int K, int Kpad)
{
    __shared__ float t[32][33];
    int nm = blockIdx.x, ob = blockIdx.y * 32, kb = blockIdx.z * 32;
    const float* Wn = W + (size_t)nm * K * EMB;
    for (int r = threadIdx.y; r < 32; r += 8) {
        int k = kb + r;
        t[r][threadIdx.x] = (k < K) ? Wn[(size_t)k * EMB + ob + threadIdx.x] : 0.f;
    }
    __syncthreads();
    size_t obase = (size_t)nm * EMB * Kpad;
    for (int r = threadIdx.y; r < 32; r += 8) {
        float v = t[threadIdx.x][r];
        __nv_bfloat16 h = __float2bfloat16(v);
        size_t d = obase + (size_t)(ob + r) * Kpad + kb + threadIdx.x;
        oh[d] = h;
        ol[d] = __float2bfloat16(v - __bfloat162float(h));
    }
}

__global__ void asplit_kernel(const float* __restrict__ A,
                              __nv_bfloat16* __restrict__ Ah, __nv_bfloat16* __restrict__ Al)
{
    int i = blockIdx.x * 256 + threadIdx.x;
    if (i < 96 * 96) {
        int m = i / 96, nn = i % 96;
        float v = (m < N_LOCS && nn < N_LOCS) ? A[m * N_LOCS + nn] : 0.f;
        __nv_bfloat16 h = __float2bfloat16(v);
        Ah[i] = h;
        Al[i] = __float2bfloat16(v - __bfloat162float(h));
    }
}

// ==================== host orchestration =====================================
static void run_stack(const float* x, int K0,
                      const float* W0, const float* b0, const float* g0, const float* be0,
                      const float* Ws, const float* bs, const float* gs, const float* bes,
                      float* bufZ, __nv_bfloat16* yh, __nv_bfloat16* yl,
                      __nv_bfloat16* acth[2], __nv_bfloat16* actl[2],
                      __nv_bfloat16* wth, __nv_bfloat16* wtl,
                      __nv_bfloat16* w0h, __nv_bfloat16* w0l,
                      __nv_bfloat16* Ah96, __nv_bfloat16* Al96, float* outF)
{
    dim3 tcb(32, 8);
    tconv_kernel<<<dim3(N_LOCS, 8, 2), tcb>>>(W0, w0h, w0l, K0, 64);
    tconv_kernel<<<dim3(7 * N_LOCS, 8, 8), tcb>>>(Ws, wth, wtl, EMB, EMB);

    const dim3 gG(BATCH / 128, EMB / 128, N_LOCS);
    const dim3 gMix(BATCH / BPC, 2);
    const int  gNorm = ELEMS / 4 / 256;

    gemm0_kernel<<<gG, 256, GEMM_SMEM>>>(x, w0h, w0l, yh, yl, K0, 64);
    mix_mma_kernel<<<gMix, 256, MIX_SMEM>>>(yh, yl, b0, bufZ, Ah96, Al96);
    stats_kernel<<<1, N_LOCS>>>(g0, be0);

    for (int bi = 1; bi <= 7; bi++) {
        int i = bi - 1;
        __nv_bfloat16* Rh = (bi >= 2) ? acth[bi & 1] : nullptr;   // act_{bi-2}
        __nv_bfloat16* Rl = (bi >= 2) ? actl[bi & 1] : nullptr;
        __nv_bfloat16* Oh = acth[(bi - 1) & 1];                   // act_{bi-1}
        __nv_bfloat16* Ol = actl[(bi - 1) & 1];
        gemm_fused_kernel<<<gG, 256, GEMM_SMEM>>>(
            bufZ, Rh, Rl, Oh, Ol,
            wth + (size_t)i * N_LOCS * EMB * EMB, wtl + (size_t)i * N_LOCS * EMB * EMB,
            yh, yl);
        mix_mma_kernel<<<gMix, 256, MIX_SMEM>>>(yh, yl, bs + (size_t)i * EMB, bufZ,
                                                Ah96, Al96);
        stats_kernel<<<1, N_LOCS>>>(gs + (size_t)i * N_LOCS, bes + (size_t)i * N_LOCS);
    }
    bn_final_kernel<<<gNorm, 256>>>((const float4*)bufZ, acth[0], actl[0],
                                    (float4*)outF);
}

extern "C" void kernel_launch(void* const* d_in, const int* in_sizes, int n_in,
                              void* d_out, int out_size)
{
    (void)in_sizes; (void)n_in; (void)out_size;
    const float* x_bo   = (const float*)d_in[0];
    const float* x_po   = (const float*)d_in[1];
    const float* A      = (const float*)d_in[2];
    const float* W0_bo  = (const float*)d_in[3];
    const float* b0_bo  = (const float*)d_in[4];
    const float* g0_bo  = (const float*)d_in[5];
    const float* be0_bo = (const float*)d_in[6];
    const float* W_bo   = (const float*)d_in[7];
    const float* b_bo   = (const float*)d_in[8];
    const float* g_bo   = (const float*)d_in[9];
    const float* be_bo  = (const float*)d_in[10];
    const float* W0_po  = (const float*)d_in[11];
    const float* b0_po  = (const float*)d_in[12];
    const float* g0_po  = (const float*)d_in[13];
    const float* be0_po = (const float*)d_in[14];
    const float* W_po   = (const float*)d_in[15];
    const float* b_po   = (const float*)d_in[16];
    const float* g_po   = (const float*)d_in[17];
    const float* be_po  = (const float*)d_in[18];
    float* out = (float*)d_out;

    cudaFuncSetAttribute(gemm0_kernel,
                         cudaFuncAttributeMaxDynamicSharedMemorySize, GEMM_SMEM);
    cudaFuncSetAttribute(gemm_fused_kernel,
                         cudaFuncAttributeMaxDynamicSharedMemorySize, GEMM_SMEM);
    cudaFuncSetAttribute(mix_mma_kernel,
                         cudaFuncAttributeMaxDynamicSharedMemorySize, MIX_SMEM);

    float *bufZ;
    __nv_bfloat16 *yh, *yl, *wth, *wtl, *w0h, *w0l, *Ah96, *Al96;
    __nv_bfloat16 *acth[2], *actl[2];
    cudaGetSymbolAddress((void**)&bufZ, g_bufZ);
    cudaGetSymbolAddress((void**)&yh, g_yh);
    cudaGetSymbolAddress((void**)&yl, g_yl);
    cudaGetSymbolAddress((void**)&acth[0], g_ah0);
    cudaGetSymbolAddress((void**)&actl[0], g_al0);
    cudaGetSymbolAddress((void**)&acth[1], g_ah1);
    cudaGetSymbolAddress((void**)&actl[1], g_al1);
    cudaGetSymbolAddress((void**)&wth, g_wth);
    cudaGetSymbolAddress((void**)&wtl, g_wtl);
    cudaGetSymbolAddress((void**)&w0h, g_w0h);
    cudaGetSymbolAddress((void**)&w0l, g_w0l);
    cudaGetSymbolAddress((void**)&Ah96, g_Ah96);
    cudaGetSymbolAddress((void**)&Al96, g_Al96);

    asplit_kernel<<<36, 256>>>(A, Ah96, Al96);

    run_stack(x_bo, 35, W0_bo, b0_bo, g0_bo, be0_bo, W_bo, b_bo, g_bo, be_bo,
              bufZ, yh, yl, acth, actl, wth, wtl, w0h, w0l, Ah96, Al96, out);
    run_stack(x_po, 40, W0_po, b0_po, g0_po, be0_po, W_po, b_po, g_po, be_po,
              bufZ, yh, yl, acth, actl, wth, wtl, w0h, w0l, Ah96, Al96, out + EMB);
}